// round 7
// baseline (speedup 1.0000x reference)
#include <cuda_runtime.h>
#include <cuda_bf16.h>
#include <cstdint>
#include <math.h>

// ---------------- problem constants ----------------
#define BB   32
#define WN   64
#define NT   50
#define CC   384
#define NH   12
#define DD   32
#define WS   7
#define HW   3136
#define SCALE 0.17677669529663687f

#define M1 (BB*WN*NT)   // 102400
#define M2 (BB*WN)      // 2048
#define M3 (BB*HW)      // 100352

// ---------------- device scratch ----------------
__device__ float g_qkv   [(size_t)M1*3*CC];
__device__ float g_out1  [(size_t)M1*CC];
__device__ float g_wintok[(size_t)M2*CC];
__device__ float g_pqk   [(size_t)M2*2*CC];
__device__ float g_pattn [(size_t)BB*NH*WN*WN];
__device__ float g_final [(size_t)M3*CC];

// ---------------- PTX helpers (baseline ISA only) ----------------
__device__ __forceinline__ uint32_t smem_u32(const void* p) {
    uint32_t r;
    asm("{ .reg .u64 t; cvta.to.shared.u64 t, %1; cvt.u32.u64 %0, t; }" : "=r"(r) : "l"(p));
    return r;
}
__device__ __forceinline__ void cpa16(uint32_t s, const void* g) {
    asm volatile("cp.async.cg.shared.global [%0], [%1], 16;" :: "r"(s), "l"(g));
}
__device__ __forceinline__ void cpa_commit() {
    asm volatile("cp.async.commit_group;" ::: "memory");
}
template<int N>
__device__ __forceinline__ void cpa_wait() {
    asm volatile("cp.async.wait_group %0;" :: "n"(N) : "memory");
}
__device__ __forceinline__ void ldsm_x4(uint32_t& r0, uint32_t& r1, uint32_t& r2, uint32_t& r3,
                                        uint32_t a) {
    asm volatile("ldmatrix.sync.aligned.m8n8.x4.shared.b16 {%0,%1,%2,%3}, [%4];"
                 : "=r"(r0), "=r"(r1), "=r"(r2), "=r"(r3) : "r"(a));
}
__device__ __forceinline__ void ldsm_x2(uint32_t& r0, uint32_t& r1, uint32_t a) {
    asm volatile("ldmatrix.sync.aligned.m8n8.x2.shared.b16 {%0,%1}, [%2];"
                 : "=r"(r0), "=r"(r1) : "r"(a));
}
// round-to-nearest fp32 -> tf32 (in-register bit pattern)
__device__ __forceinline__ uint32_t to_tf32(uint32_t x) {
    uint32_t r; float f = __uint_as_float(x);
    asm("cvt.rna.tf32.f32 %0, %1;" : "=r"(r) : "f"(f));
    return r;
}
__device__ __forceinline__ void mma_tf32(float* d, const uint32_t* a, const uint32_t* b) {
    asm volatile(
        "mma.sync.aligned.m16n8k8.row.col.f32.tf32.tf32.f32 "
        "{%0,%1,%2,%3}, {%4,%5,%6,%7}, {%8,%9}, {%0,%1,%2,%3};"
        : "+f"(d[0]), "+f"(d[1]), "+f"(d[2]), "+f"(d[3])
        : "r"(a[0]), "r"(a[1]), "r"(a[2]), "r"(a[3]), "r"(b[0]), "r"(b[1]));
}

// ---------------- tf32 HMMA GEMM: C[m,n] = sum_k A[m,k]*W[n,k] (+bias) ------
// 128x128x32 CTA tile, 8 warps (2m x 4n), 64x32 warp tile, cp.async double
// buffer, 2 CTAs/SM. A,W are plain fp32; fragments loaded via b16-view
// ldmatrix and cvt.rna to tf32.
#define BKF   32                       // k per chunk (fp32 elems)
#define PITCHB 144                     // bytes per smem row (32 fp32 + 16B pad)
#define PLANE (128 * PITCHB)           // 18432 B
#define BUF_B (2 * PLANE)              // A plane + B plane
#define SMEM_TOT (2 * BUF_B)           // 73728 B

__device__ __forceinline__ void load_plane(uint32_t dst, const float* __restrict__ G,
                                           int row0, int k0, int K, int tid)
{
    #pragma unroll
    for (int i = 0; i < 4; i++) {
        int seg = tid + i * 256;       // 0..1023
        int r = seg >> 3, u = seg & 7;
        cpa16(dst + r * PITCHB + u * 16, G + (size_t)(row0 + r) * K + k0 + u * 4);
    }
}

__global__ void __launch_bounds__(256, 2)
mma_gemm(const float* __restrict__ A, const float* __restrict__ W,
         const float* __restrict__ bias, float* __restrict__ C, int N, int K)
{
    extern __shared__ __align__(128) char dsm[];
    const int tid  = threadIdx.x;
    const int lane = tid & 31;
    const int wid  = tid >> 5;
    const int wm   = wid & 1;          // m offset 64*wm
    const int wn   = wid >> 1;         // n offset 32*wn
    const int m0 = blockIdx.y * 128;
    const int n0 = blockIdx.x * 128;
    const uint32_t sb = smem_u32(dsm);

    float acc[4][4][4];
    #pragma unroll
    for (int mi = 0; mi < 4; mi++)
        #pragma unroll
        for (int ni = 0; ni < 4; ni++)
            #pragma unroll
            for (int f = 0; f < 4; f++) acc[mi][ni][f] = 0.f;

    const int NC = K / BKF;            // 12

    {
        load_plane(sb + 0 * PLANE, A, m0, 0, K, tid);
        load_plane(sb + 1 * PLANE, W, n0, 0, K, tid);
        cpa_commit();
    }

    // b16-view ldmatrix lane addressing (constant across chunks)
    // A quadrants: row = lane&15, colByte = (lane>>4)*16
    const uint32_t a_row = wm * 64 + (lane & 15);
    const uint32_t a_cb  = (lane >> 4) * 16;
    // B quadrants (x2): row = lane&7, colByte = ((lane>>3)&1)*16
    const uint32_t b_row = wn * 32 + (lane & 7);
    const uint32_t b_cb  = ((lane >> 3) & 1) * 16;

    for (int c = 0; c < NC; c++) {
        if (c + 1 < NC) {
            uint32_t buf = sb + ((c + 1) & 1) * BUF_B;
            load_plane(buf + 0 * PLANE, A, m0, (c + 1) * BKF, K, tid);
            load_plane(buf + 1 * PLANE, W, n0, (c + 1) * BKF, K, tid);
            cpa_commit();
            cpa_wait<1>();
        } else {
            cpa_wait<0>();
        }
        __syncthreads();

        const uint32_t buf = sb + (c & 1) * BUF_B;
        #pragma unroll
        for (int ks = 0; ks < 4; ks++) {           // 4 x k8 per chunk
            uint32_t a[4][4], b[4][2];
            #pragma unroll
            for (int mi = 0; mi < 4; mi++) {
                uint32_t off = (a_row + mi * 16) * PITCHB + ks * 32 + a_cb;
                ldsm_x4(a[mi][0], a[mi][1], a[mi][2], a[mi][3], buf + 0 * PLANE + off);
                #pragma unroll
                for (int f = 0; f < 4; f++) a[mi][f] = to_tf32(a[mi][f]);
            }
            #pragma unroll
            for (int ni = 0; ni < 4; ni++) {
                uint32_t off = (b_row + ni * 8) * PITCHB + ks * 32 + b_cb;
                ldsm_x2(b[ni][0], b[ni][1], buf + 1 * PLANE + off);
                b[ni][0] = to_tf32(b[ni][0]);
                b[ni][1] = to_tf32(b[ni][1]);
            }
            #pragma unroll
            for (int mi = 0; mi < 4; mi++)
                #pragma unroll
                for (int ni = 0; ni < 4; ni++)
                    mma_tf32(acc[mi][ni], a[mi], b[ni]);
        }
        __syncthreads();
    }

    const int rr = lane >> 2, cp = (lane & 3) * 2;
    #pragma unroll
    for (int mi = 0; mi < 4; mi++) {
        int row = m0 + wm * 64 + mi * 16 + rr;
        #pragma unroll
        for (int ni = 0; ni < 4; ni++) {
            int col = n0 + wn * 32 + ni * 8 + cp;
            float b0 = 0.f, b1 = 0.f;
            if (bias) { b0 = bias[col]; b1 = bias[col + 1]; }
            float* p = C + (size_t)row * N + col;
            p[0] = acc[mi][ni][0] + b0;
            p[1] = acc[mi][ni][1] + b1;
            float* q = p + (size_t)8 * N;
            q[0] = acc[mi][ni][2] + b0;
            q[1] = acc[mi][ni][3] + b1;
        }
    }
}

// ---------------- K2: per-(window, head) attention + residual (best) --------
__global__ void win_attn_kernel(const float* __restrict__ qkv,
                                const float* __restrict__ x,
                                float* __restrict__ out1)
{
    const int bw = blockIdx.x;
    const int hh = blockIdx.y;
    __shared__ float q[NT][32];
    __shared__ float k[NT][33];
    __shared__ float v[NT][32];
    __shared__ float at[NT][NT];
    const int tid = threadIdx.x; // 256

    const float* base = qkv + (size_t)bw * NT * (3 * CC) + hh * DD;
    for (int idx = tid; idx < NT * 32; idx += 256) {
        int i = idx >> 5, dd = idx & 31;
        const float* row = base + (size_t)i * (3 * CC);
        q[i][dd] = row[dd];
        k[i][dd] = row[CC + dd];
        v[i][dd] = row[2 * CC + dd];
    }
    __syncthreads();

    for (int idx = tid; idx < NT * NT; idx += 256) {
        int i = idx / NT, j = idx % NT;
        float s = 0.f;
        #pragma unroll
        for (int d = 0; d < 32; d++) s += q[i][d] * k[j][d];
        at[i][j] = s * SCALE;
    }
    __syncthreads();

    if (tid < NT) {
        float m = -1e30f;
        for (int j = 0; j < NT; j++) m = fmaxf(m, at[tid][j]);
        float sum = 0.f;
        for (int j = 0; j < NT; j++) { float e = __expf(at[tid][j] - m); at[tid][j] = e; sum += e; }
        float inv = 1.f / sum;
        for (int j = 0; j < NT; j++) at[tid][j] *= inv;
    }
    __syncthreads();

    for (int idx = tid; idx < NT * 32; idx += 256) {
        int i = idx >> 5, dd = idx & 31;
        float s = 0.f;
        #pragma unroll 10
        for (int j = 0; j < NT; j++) s += at[i][j] * v[j][dd];
        size_t o = (size_t)bw * NT * CC + (size_t)i * CC + hh * DD + dd;
        out1[o] = s + x[o];
    }
}

// ---------------- K3a: LayerNorm + exact GELU (fp32 out) --------------------
__global__ void ln_gelu_kernel(const float* __restrict__ out1,
                               const float* __restrict__ g,
                               const float* __restrict__ b,
                               float* __restrict__ wintok)
{
    const int bw = blockIdx.x;
    const int tid = threadIdx.x; // 128
    const float* row = out1 + (size_t)bw * NT * CC;
    float vv[3], s = 0.f, s2 = 0.f;
    #pragma unroll
    for (int i = 0; i < 3; i++) {
        vv[i] = row[tid + i * 128];
        s += vv[i]; s2 += vv[i] * vv[i];
    }
    __shared__ float rs[4], rs2[4];
    #pragma unroll
    for (int o = 16; o; o >>= 1) {
        s  += __shfl_down_sync(0xFFFFFFFFu, s,  o);
        s2 += __shfl_down_sync(0xFFFFFFFFu, s2, o);
    }
    if ((tid & 31) == 0) { rs[tid >> 5] = s; rs2[tid >> 5] = s2; }
    __syncthreads();
    float S  = rs[0] + rs[1] + rs[2] + rs[3];
    float S2 = rs2[0] + rs2[1] + rs2[2] + rs2[3];
    float mean = S / (float)CC;
    float var  = S2 / (float)CC - mean * mean;
    float inv  = rsqrtf(var + 1e-5f);
    #pragma unroll
    for (int i = 0; i < 3; i++) {
        int c = tid + i * 128;
        float nz = (vv[i] - mean) * inv * g[c] + b[c];
        float ge = 0.5f * nz * (1.f + erff(nz * 0.70710678118654752f));
        wintok[(size_t)bw * CC + c] = ge;
    }
}

// ---------------- K4: pooled attention softmax ------------------------------
__global__ void pool_attn_kernel(const float* __restrict__ pqk,
                                 float* __restrict__ pattn)
{
    const int b = blockIdx.x, hh = blockIdx.y;
    __shared__ float pq[WN][32];
    __shared__ float pk[WN][33];
    __shared__ float sc[WN][WN];
    const int tid = threadIdx.x; // 256

    for (int idx = tid; idx < WN * 32; idx += 256) {
        int w = idx >> 5, d = idx & 31;
        size_t base = (size_t)(b * WN + w) * (2 * CC) + hh * DD + d;
        pq[w][d] = pqk[base];
        pk[w][d] = pqk[base + CC];
    }
    __syncthreads();

    for (int idx = tid; idx < WN * WN; idx += 256) {
        int w = idx >> 6, vv = idx & 63;
        float s = 0.f;
        #pragma unroll
        for (int d = 0; d < 32; d++) s += pq[w][d] * pk[vv][d];
        sc[w][vv] = s * SCALE;
    }
    __syncthreads();

    if (tid < WN) {
        float m = -1e30f;
        for (int j = 0; j < WN; j++) m = fmaxf(m, sc[tid][j]);
        float sum = 0.f;
        for (int j = 0; j < WN; j++) { float e = __expf(sc[tid][j] - m); sc[tid][j] = e; sum += e; }
        float inv = 1.f / sum;
        for (int j = 0; j < WN; j++) sc[tid][j] *= inv;
    }
    __syncthreads();

    float* dst = pattn + (size_t)(b * NH + hh) * WN * WN;
    for (int idx = tid; idx < WN * WN; idx += 256) dst[idx] = sc[idx >> 6][idx & 63];
}

// ---------------- K5: PSA mix + residual + rearrange (fp32 out) -------------
__global__ void psa_kernel(const float* __restrict__ pattn,
                           const float* __restrict__ out1,
                           float* __restrict__ finalb)
{
    const int bh = blockIdx.x;
    const int b = bh / NH, hh = bh % NH;
    const int si = blockIdx.y;
    __shared__ float sp[WN][WN];
    const int tid = threadIdx.x; // 224

    const float* src = pattn + (size_t)bh * WN * WN;
    for (int idx = tid; idx < WN * WN; idx += 224) sp[idx >> 6][idx & 63] = src[idx];
    __syncthreads();

    const int sj = tid >> 5, dd = tid & 31;
    const int s = si * 7 + sj;
    const int col = hh * DD + dd;

    float acc[WN];
    #pragma unroll
    for (int w = 0; w < WN; w++) acc[w] = 0.f;

    for (int vv = 0; vv < WN; vv++) {
        float bv = out1[((size_t)(b * WN + vv) * NT + s + 1) * CC + col];
        #pragma unroll
        for (int w = 0; w < WN; w++) acc[w] += sp[w][vv] * bv;
    }

    for (int w = 0; w < WN; w++) {
        float ax = out1[((size_t)(b * WN + w) * NT + s + 1) * CC + col];
        int hi = w >> 3, wi = w & 7;
        int y = hi * WS + si, xx = wi * WS + sj;
        finalb[((size_t)b * HW + y * 56 + xx) * CC + col] = acc[w] + ax;
    }
}

// ---------------- launch ----------------
extern "C" void kernel_launch(void* const* d_in, const int* in_sizes, int n_in,
                              void* d_out, int out_size)
{
    const float* x      = (const float*)d_in[0];
    const float* w_qkv  = (const float*)d_in[3];
    const float* w_qk   = (const float*)d_in[4];
    const float* ln_g   = (const float*)d_in[5];
    const float* ln_b   = (const float*)d_in[6];
    const float* w_proj = (const float*)d_in[7];
    const float* b_proj = (const float*)d_in[8];
    float* out = (float*)d_out;

    float *p_qkv, *p_out1, *p_wintok, *p_pqk, *p_pattn, *p_final;
    cudaGetSymbolAddress((void**)&p_qkv,    g_qkv);
    cudaGetSymbolAddress((void**)&p_out1,   g_out1);
    cudaGetSymbolAddress((void**)&p_wintok, g_wintok);
    cudaGetSymbolAddress((void**)&p_pqk,    g_pqk);
    cudaGetSymbolAddress((void**)&p_pattn,  g_pattn);
    cudaGetSymbolAddress((void**)&p_final,  g_final);

    cudaFuncSetAttribute(mma_gemm, cudaFuncAttributeMaxDynamicSharedMemorySize, SMEM_TOT);

    // K1: qkv = x @ w_qkv^T  (102400 x 1152, K=384)
    mma_gemm<<<dim3(3 * CC / 128, M1 / 128), 256, SMEM_TOT>>>(
        x, w_qkv, nullptr, p_qkv, 3 * CC, CC);

    // K2: window attention + residual
    win_attn_kernel<<<dim3(BB * WN, NH), 256>>>(p_qkv, x, p_out1);

    // K3a: LN + GELU
    ln_gelu_kernel<<<M2, 128>>>(p_out1, ln_g, ln_b, p_wintok);

    // K3b: pqk = wintok @ w_qk^T  (2048 x 768, K=384)
    mma_gemm<<<dim3(2 * CC / 128, M2 / 128), 256, SMEM_TOT>>>(
        p_wintok, w_qk, nullptr, p_pqk, 2 * CC, CC);

    // K4: pooled attention softmax
    pool_attn_kernel<<<dim3(BB, NH), 256>>>(p_pqk, p_pattn);

    // K5: PSA mix + residual + rearrange
    psa_kernel<<<dim3(BB * NH, WS), 224>>>(p_pattn, p_out1, p_final);

    // K6: out = final @ w_proj^T + b_proj  (100352 x 384, K=384)
    mma_gemm<<<dim3(CC / 128, M3 / 128), 256, SMEM_TOT>>>(
        p_final, w_proj, b_proj, out, CC, CC);
}

// round 8
// speedup vs baseline: 1.5093x; 1.5093x over previous
#include <cuda_runtime.h>
#include <cuda_bf16.h>
#include <cstdint>
#include <math.h>

// ---------------- problem constants ----------------
#define BB   32
#define WN   64
#define NT   50
#define CC   384
#define NH   12
#define DD   32
#define WS   7
#define HW   3136
#define SCALE 0.17677669529663687f

#define M1 (BB*WN*NT)   // 102400
#define M2 (BB*WN)      // 2048
#define M3 (BB*HW)      // 100352

// ---------------- device scratch ----------------
__device__ float g_qkv  [(size_t)M1*3*CC];
__device__ float g_out1 [(size_t)M1*CC];
__device__ float g_pqk  [(size_t)M2*2*CC];
__device__ float g_pattn[(size_t)BB*NH*WN*WN];

__device__ __nv_bfloat16 g_x_hi[(size_t)M1*CC],  g_x_lo[(size_t)M1*CC];
__device__ __nv_bfloat16 g_wqkv_hi[3*CC*CC],     g_wqkv_lo[3*CC*CC];
__device__ __nv_bfloat16 g_wqk_hi [2*CC*CC],     g_wqk_lo [2*CC*CC];
__device__ __nv_bfloat16 g_wproj_hi[CC*CC],      g_wproj_lo[CC*CC];
__device__ __nv_bfloat16 g_wt_hi[(size_t)M2*CC], g_wt_lo[(size_t)M2*CC];
__device__ __nv_bfloat16 g_fin_hi[(size_t)M3*CC],g_fin_lo[(size_t)M3*CC];

// ---------------- PTX helpers (baseline ISA only) ----------------
__device__ __forceinline__ uint32_t smem_u32(const void* p) {
    uint32_t r;
    asm("{ .reg .u64 t; cvta.to.shared.u64 t, %1; cvt.u32.u64 %0, t; }" : "=r"(r) : "l"(p));
    return r;
}
__device__ __forceinline__ void cpa16(uint32_t s, const void* g) {
    asm volatile("cp.async.cg.shared.global [%0], [%1], 16;" :: "r"(s), "l"(g));
}
__device__ __forceinline__ void cpa_commit() {
    asm volatile("cp.async.commit_group;" ::: "memory");
}
template<int N>
__device__ __forceinline__ void cpa_wait() {
    asm volatile("cp.async.wait_group %0;" :: "n"(N) : "memory");
}
__device__ __forceinline__ void ldsm_x4(uint32_t& r0, uint32_t& r1, uint32_t& r2, uint32_t& r3,
                                        uint32_t a) {
    asm volatile("ldmatrix.sync.aligned.m8n8.x4.shared.b16 {%0,%1,%2,%3}, [%4];"
                 : "=r"(r0), "=r"(r1), "=r"(r2), "=r"(r3) : "r"(a));
}
__device__ __forceinline__ void ldsm_x2(uint32_t& r0, uint32_t& r1, uint32_t a) {
    asm volatile("ldmatrix.sync.aligned.m8n8.x2.shared.b16 {%0,%1}, [%2];"
                 : "=r"(r0), "=r"(r1) : "r"(a));
}
__device__ __forceinline__ void mma_bf16(float* d, const uint32_t* a, const uint32_t* b) {
    asm volatile(
        "mma.sync.aligned.m16n8k16.row.col.f32.bf16.bf16.f32 "
        "{%0,%1,%2,%3}, {%4,%5,%6,%7}, {%8,%9}, {%0,%1,%2,%3};"
        : "+f"(d[0]), "+f"(d[1]), "+f"(d[2]), "+f"(d[3])
        : "r"(a[0]), "r"(a[1]), "r"(a[2]), "r"(a[3]), "r"(b[0]), "r"(b[1]));
}

// ---------------- bf16 hi/lo split ----------------
__global__ void split_kernel(const float4* __restrict__ in,
                             __nv_bfloat16* __restrict__ hi,
                             __nv_bfloat16* __restrict__ lo, int n4)
{
    int i = blockIdx.x * 256 + threadIdx.x;
    if (i >= n4) return;
    float4 v = in[i];
    float xs[4] = {v.x, v.y, v.z, v.w};
    union { __nv_bfloat16 b[4]; uint2 u; } H, L;
    #pragma unroll
    for (int j = 0; j < 4; j++) {
        __nv_bfloat16 h = __float2bfloat16(xs[j]);
        H.b[j] = h;
        L.b[j] = __float2bfloat16(xs[j] - __bfloat162float(h));
    }
    *reinterpret_cast<uint2*>(hi + (size_t)i * 4) = H.u;
    *reinterpret_cast<uint2*>(lo + (size_t)i * 4) = L.u;
}

// ---------------- bf16x3 HMMA GEMM (R5 best: 2 CTAs/SM) ----------------
#define BKH   32
#define PITCH 80
#define PLANE (128 * PITCH)
#define BUF_B (4 * PLANE)
#define SMEM_TOT (2 * BUF_B)

__device__ __forceinline__ void load_plane(uint32_t dst, const __nv_bfloat16* __restrict__ G,
                                           int row0, int k0, int K, int tid)
{
    #pragma unroll
    for (int i = 0; i < 2; i++) {
        int seg = tid + i * 256;
        int r = seg >> 2, u = seg & 3;
        cpa16(dst + r * PITCH + u * 16, G + (size_t)(row0 + r) * K + k0 + u * 8);
    }
}

__global__ void __launch_bounds__(256, 2)
mma_gemm(const __nv_bfloat16* __restrict__ Ahi, const __nv_bfloat16* __restrict__ Alo,
         const __nv_bfloat16* __restrict__ Bhi, const __nv_bfloat16* __restrict__ Blo,
         const float* __restrict__ bias, float* __restrict__ C, int N, int K)
{
    extern __shared__ __align__(128) char dsm[];
    const int tid  = threadIdx.x;
    const int lane = tid & 31;
    const int wid  = tid >> 5;
    const int wm   = wid & 1;
    const int wn   = wid >> 1;
    const int m0 = blockIdx.y * 128;
    const int n0 = blockIdx.x * 128;
    const uint32_t sb = smem_u32(dsm);

    float acc[4][4][4];
    #pragma unroll
    for (int mi = 0; mi < 4; mi++)
        #pragma unroll
        for (int ni = 0; ni < 4; ni++)
            #pragma unroll
            for (int f = 0; f < 4; f++) acc[mi][ni][f] = 0.f;

    const int NC = K / BKH;

    {
        uint32_t buf = sb;
        load_plane(buf + 0 * PLANE, Ahi, m0, 0, K, tid);
        load_plane(buf + 1 * PLANE, Alo, m0, 0, K, tid);
        load_plane(buf + 2 * PLANE, Bhi, n0, 0, K, tid);
        load_plane(buf + 3 * PLANE, Blo, n0, 0, K, tid);
        cpa_commit();
    }

    const int l16 = lane & 15;
    const uint32_t a_row = wm * 64 + l16;
    const uint32_t a_cb  = ((lane >> 4) & 1) * 16;
    const uint32_t b_row = wn * 32 + (l16 & 7);
    const uint32_t b_cb  = (l16 >> 3) * 16;

    for (int c = 0; c < NC; c++) {
        if (c + 1 < NC) {
            uint32_t buf = sb + ((c + 1) & 1) * BUF_B;
            load_plane(buf + 0 * PLANE, Ahi, m0, (c + 1) * BKH, K, tid);
            load_plane(buf + 1 * PLANE, Alo, m0, (c + 1) * BKH, K, tid);
            load_plane(buf + 2 * PLANE, Bhi, n0, (c + 1) * BKH, K, tid);
            load_plane(buf + 3 * PLANE, Blo, n0, (c + 1) * BKH, K, tid);
            cpa_commit();
            cpa_wait<1>();
        } else {
            cpa_wait<0>();
        }
        __syncthreads();

        const uint32_t buf = sb + (c & 1) * BUF_B;
        #pragma unroll
        for (int ks = 0; ks < 2; ks++) {
            uint32_t ah[4][4], al[4][4], bh[4][2], bl[4][2];
            #pragma unroll
            for (int mi = 0; mi < 4; mi++) {
                uint32_t off = (a_row + mi * 16) * PITCH + ks * 32 + a_cb;
                ldsm_x4(ah[mi][0], ah[mi][1], ah[mi][2], ah[mi][3], buf + 0 * PLANE + off);
                ldsm_x4(al[mi][0], al[mi][1], al[mi][2], al[mi][3], buf + 1 * PLANE + off);
            }
            #pragma unroll
            for (int ni = 0; ni < 4; ni++) {
                uint32_t off = (b_row + ni * 8) * PITCH + ks * 32 + b_cb;
                ldsm_x2(bh[ni][0], bh[ni][1], buf + 2 * PLANE + off);
                ldsm_x2(bl[ni][0], bl[ni][1], buf + 3 * PLANE + off);
            }
            #pragma unroll
            for (int mi = 0; mi < 4; mi++)
                #pragma unroll
                for (int ni = 0; ni < 4; ni++) {
                    mma_bf16(acc[mi][ni], ah[mi], bh[ni]);
                    mma_bf16(acc[mi][ni], ah[mi], bl[ni]);
                    mma_bf16(acc[mi][ni], al[mi], bh[ni]);
                }
        }
        __syncthreads();
    }

    const int rr = lane >> 2, cp = (lane & 3) * 2;
    #pragma unroll
    for (int mi = 0; mi < 4; mi++) {
        int row = m0 + wm * 64 + mi * 16 + rr;
        #pragma unroll
        for (int ni = 0; ni < 4; ni++) {
            int col = n0 + wn * 32 + ni * 8 + cp;
            float b0 = 0.f, b1 = 0.f;
            if (bias) { b0 = bias[col]; b1 = bias[col + 1]; }
            float* p = C + (size_t)row * N + col;
            p[0] = acc[mi][ni][0] + b0;
            p[1] = acc[mi][ni][1] + b1;
            float* q = p + (size_t)8 * N;
            q[0] = acc[mi][ni][2] + b0;
            q[1] = acc[mi][ni][3] + b1;
        }
    }
}

// ---------------- K2 v3: window attention + residual ------------------------
// Vectorized smem (pitch 36 for q/k/v, 52 for at), flat unit loops with 4-row
// i-groups so k/v rows are reused x4, warp-parallel softmax.
#define QP 36
#define AP 52
__global__ void __launch_bounds__(256)
win_attn_kernel(const float* __restrict__ qkv,
                const float* __restrict__ x,
                float* __restrict__ out1)
{
    const int bw = blockIdx.x;
    const int hh = blockIdx.y;
    __shared__ __align__(16) float q[NT][QP];
    __shared__ __align__(16) float k[NT][QP];
    __shared__ __align__(16) float v[NT][QP];
    __shared__ __align__(16) float at[NT][AP];
    const int tid  = threadIdx.x;
    const int warp = tid >> 5, lane = tid & 31;

    // load q,k,v as float4 (1200 segments)
    {
        const float* base = qkv + (size_t)bw * NT * (3 * CC) + hh * DD;
        for (int seg = tid; seg < NT * 24; seg += 256) {
            int i = seg / 24, r = seg % 24;
            int t = r >> 3, u = r & 7;
            float4 val = *reinterpret_cast<const float4*>(base + (size_t)i * (3 * CC) + t * CC + u * 4);
            float* dst = (t == 0 ? &q[i][u * 4] : t == 1 ? &k[i][u * 4] : &v[i][u * 4]);
            *reinterpret_cast<float4*>(dst) = val;
        }
    }
    __syncthreads();

    // scores: unit = (ig [13 groups of 4 rows], j [50]) = 650 units
    for (int u = tid; u < 650; u += 256) {
        const int ig = u / 50, j = u % 50;
        const int i0 = ig * 4;
        const int i1 = (i0 + 1 < NT) ? i0 + 1 : NT - 1;
        const int i2 = (i0 + 2 < NT) ? i0 + 2 : NT - 1;
        const int i3 = (i0 + 3 < NT) ? i0 + 3 : NT - 1;
        float a0 = 0.f, a1 = 0.f, a2 = 0.f, a3 = 0.f;
        #pragma unroll
        for (int d4 = 0; d4 < 8; d4++) {
            float4 kv = *reinterpret_cast<const float4*>(&k[j][d4 * 4]);
            float4 q0 = *reinterpret_cast<const float4*>(&q[i0][d4 * 4]);
            float4 q1 = *reinterpret_cast<const float4*>(&q[i1][d4 * 4]);
            float4 q2 = *reinterpret_cast<const float4*>(&q[i2][d4 * 4]);
            float4 q3 = *reinterpret_cast<const float4*>(&q[i3][d4 * 4]);
            a0 += q0.x * kv.x + q0.y * kv.y + q0.z * kv.z + q0.w * kv.w;
            a1 += q1.x * kv.x + q1.y * kv.y + q1.z * kv.z + q1.w * kv.w;
            a2 += q2.x * kv.x + q2.y * kv.y + q2.z * kv.z + q2.w * kv.w;
            a3 += q3.x * kv.x + q3.y * kv.y + q3.z * kv.z + q3.w * kv.w;
        }
        at[i0][j] = a0 * SCALE;
        if (i0 + 1 < NT) at[i0 + 1][j] = a1 * SCALE;
        if (i0 + 2 < NT) at[i0 + 2][j] = a2 * SCALE;
        if (i0 + 3 < NT) at[i0 + 3][j] = a3 * SCALE;
    }
    __syncthreads();

    // softmax: warp per row
    for (int i = warp; i < NT; i += 8) {
        float a0 = at[i][lane];
        float a1 = (lane < 18) ? at[i][32 + lane] : -1e30f;
        float m = fmaxf(a0, a1);
        #pragma unroll
        for (int o = 16; o; o >>= 1) m = fmaxf(m, __shfl_xor_sync(0xFFFFFFFFu, m, o));
        float e0 = __expf(a0 - m);
        float e1 = (lane < 18) ? __expf(a1 - m) : 0.f;
        float s = e0 + e1;
        #pragma unroll
        for (int o = 16; o; o >>= 1) s += __shfl_xor_sync(0xFFFFFFFFu, s, o);
        float inv = 1.f / s;
        at[i][lane] = e0 * inv;
        if (lane < 18) at[i][32 + lane] = e1 * inv;
    }
    __syncthreads();

    // AV: unit = (ig [13], dd [32]) = 416 units
    for (int u = tid; u < 416; u += 256) {
        const int ig = u >> 5, dd = u & 31;
        const int i0 = ig * 4;
        const int i1 = (i0 + 1 < NT) ? i0 + 1 : NT - 1;
        const int i2 = (i0 + 2 < NT) ? i0 + 2 : NT - 1;
        const int i3 = (i0 + 3 < NT) ? i0 + 3 : NT - 1;
        float a0 = 0.f, a1 = 0.f, a2 = 0.f, a3 = 0.f;
        #pragma unroll
        for (int j4 = 0; j4 < 12; j4++) {
            float v0 = v[j4 * 4 + 0][dd], v1 = v[j4 * 4 + 1][dd];
            float v2 = v[j4 * 4 + 2][dd], v3 = v[j4 * 4 + 3][dd];
            float4 p0 = *reinterpret_cast<const float4*>(&at[i0][j4 * 4]);
            float4 p1 = *reinterpret_cast<const float4*>(&at[i1][j4 * 4]);
            float4 p2 = *reinterpret_cast<const float4*>(&at[i2][j4 * 4]);
            float4 p3 = *reinterpret_cast<const float4*>(&at[i3][j4 * 4]);
            a0 += p0.x * v0 + p0.y * v1 + p0.z * v2 + p0.w * v3;
            a1 += p1.x * v0 + p1.y * v1 + p1.z * v2 + p1.w * v3;
            a2 += p2.x * v0 + p2.y * v1 + p2.z * v2 + p2.w * v3;
            a3 += p3.x * v0 + p3.y * v1 + p3.z * v2 + p3.w * v3;
        }
        {
            float v0 = v[48][dd], v1 = v[49][dd];
            a0 += at[i0][48] * v0 + at[i0][49] * v1;
            a1 += at[i1][48] * v0 + at[i1][49] * v1;
            a2 += at[i2][48] * v0 + at[i2][49] * v1;
            a3 += at[i3][48] * v0 + at[i3][49] * v1;
        }
        const size_t ob = (size_t)bw * NT * CC + hh * DD + dd;
        float r[4] = {a0, a1, a2, a3};
        #pragma unroll
        for (int t = 0; t < 4; t++) {
            int i = i0 + t;
            if (i < NT) {
                size_t o = ob + (size_t)i * CC;
                out1[o] = r[t] + x[o];
            }
        }
    }
}

// ---------------- K3a: LayerNorm + exact GELU -> bf16 hi/lo -----------------
__global__ void ln_gelu_kernel(const float* __restrict__ out1,
                               const float* __restrict__ g,
                               const float* __restrict__ b,
                               __nv_bfloat16* __restrict__ wt_hi,
                               __nv_bfloat16* __restrict__ wt_lo)
{
    const int bw = blockIdx.x;
    const int tid = threadIdx.x; // 128
    const float* row = out1 + (size_t)bw * NT * CC;
    float vv[3], s = 0.f, s2 = 0.f;
    #pragma unroll
    for (int i = 0; i < 3; i++) {
        vv[i] = row[tid + i * 128];
        s += vv[i]; s2 += vv[i] * vv[i];
    }
    __shared__ float rs[4], rs2[4];
    #pragma unroll
    for (int o = 16; o; o >>= 1) {
        s  += __shfl_down_sync(0xFFFFFFFFu, s,  o);
        s2 += __shfl_down_sync(0xFFFFFFFFu, s2, o);
    }
    if ((tid & 31) == 0) { rs[tid >> 5] = s; rs2[tid >> 5] = s2; }
    __syncthreads();
    float S  = rs[0] + rs[1] + rs[2] + rs[3];
    float S2 = rs2[0] + rs2[1] + rs2[2] + rs2[3];
    float mean = S / (float)CC;
    float var  = S2 / (float)CC - mean * mean;
    float inv  = rsqrtf(var + 1e-5f);
    #pragma unroll
    for (int i = 0; i < 3; i++) {
        int c = tid + i * 128;
        float nz = (vv[i] - mean) * inv * g[c] + b[c];
        float ge = 0.5f * nz * (1.f + erff(nz * 0.70710678118654752f));
        __nv_bfloat16 h = __float2bfloat16(ge);
        wt_hi[(size_t)bw * CC + c] = h;
        wt_lo[(size_t)bw * CC + c] = __float2bfloat16(ge - __bfloat162float(h));
    }
}

// ---------------- K4: pooled attention softmax ------------------------------
__global__ void pool_attn_kernel(const float* __restrict__ pqk,
                                 float* __restrict__ pattn)
{
    const int b = blockIdx.x, hh = blockIdx.y;
    __shared__ float pq[WN][32];
    __shared__ float pk[WN][33];
    __shared__ float sc[WN][WN];
    const int tid = threadIdx.x; // 256

    for (int idx = tid; idx < WN * 32; idx += 256) {
        int w = idx >> 5, d = idx & 31;
        size_t base = (size_t)(b * WN + w) * (2 * CC) + hh * DD + d;
        pq[w][d] = pqk[base];
        pk[w][d] = pqk[base + CC];
    }
    __syncthreads();

    for (int idx = tid; idx < WN * WN; idx += 256) {
        int w = idx >> 6, vv = idx & 63;
        float s = 0.f;
        #pragma unroll
        for (int d = 0; d < 32; d++) s += pq[w][d] * pk[vv][d];
        sc[w][vv] = s * SCALE;
    }
    __syncthreads();

    if (tid < WN) {
        float m = -1e30f;
        for (int j = 0; j < WN; j++) m = fmaxf(m, sc[tid][j]);
        float sum = 0.f;
        for (int j = 0; j < WN; j++) { float e = __expf(sc[tid][j] - m); sc[tid][j] = e; sum += e; }
        float inv = 1.f / sum;
        for (int j = 0; j < WN; j++) sc[tid][j] *= inv;
    }
    __syncthreads();

    float* dst = pattn + (size_t)(b * NH + hh) * WN * WN;
    for (int idx = tid; idx < WN * WN; idx += 256) dst[idx] = sc[idx >> 6][idx & 63];
}

// ---------------- K5: PSA mix + residual + rearrange -> bf16 hi/lo (best) ---
__global__ void psa_kernel(const float* __restrict__ pattn,
                           const float* __restrict__ out1,
                           __nv_bfloat16* __restrict__ fin_hi,
                           __nv_bfloat16* __restrict__ fin_lo)
{
    const int bh = blockIdx.x;
    const int b = bh / NH, hh = bh % NH;
    const int si = blockIdx.y;
    __shared__ float sp[WN][WN];
    const int tid = threadIdx.x; // 224

    const float* src = pattn + (size_t)bh * WN * WN;
    for (int idx = tid; idx < WN * WN; idx += 224) sp[idx >> 6][idx & 63] = src[idx];
    __syncthreads();

    const int sj = tid >> 5, dd = tid & 31;
    const int s = si * 7 + sj;
    const int col = hh * DD + dd;

    float acc[WN];
    #pragma unroll
    for (int w = 0; w < WN; w++) acc[w] = 0.f;

    for (int vv = 0; vv < WN; vv++) {
        float bv = out1[((size_t)(b * WN + vv) * NT + s + 1) * CC + col];
        #pragma unroll
        for (int w = 0; w < WN; w++) acc[w] += sp[w][vv] * bv;
    }

    for (int w = 0; w < WN; w++) {
        float ax = out1[((size_t)(b * WN + w) * NT + s + 1) * CC + col];
        int hi = w >> 3, wi = w & 7;
        int y = hi * WS + si, xx = wi * WS + sj;
        size_t o = ((size_t)b * HW + y * 56 + xx) * CC + col;
        float f = acc[w] + ax;
        __nv_bfloat16 h = __float2bfloat16(f);
        fin_hi[o] = h;
        fin_lo[o] = __float2bfloat16(f - __bfloat162float(h));
    }
}

// ---------------- launch ----------------
extern "C" void kernel_launch(void* const* d_in, const int* in_sizes, int n_in,
                              void* d_out, int out_size)
{
    const float* x      = (const float*)d_in[0];
    const float* w_qkv  = (const float*)d_in[3];
    const float* w_qk   = (const float*)d_in[4];
    const float* ln_g   = (const float*)d_in[5];
    const float* ln_b   = (const float*)d_in[6];
    const float* w_proj = (const float*)d_in[7];
    const float* b_proj = (const float*)d_in[8];
    float* out = (float*)d_out;

    float *p_qkv, *p_out1, *p_pqk, *p_pattn;
    __nv_bfloat16 *p_xh, *p_xl, *p_wqkvh, *p_wqkvl, *p_wqkh, *p_wqkl,
                  *p_wprojh, *p_wprojl, *p_wth, *p_wtl, *p_finh, *p_finl;
    cudaGetSymbolAddress((void**)&p_qkv,   g_qkv);
    cudaGetSymbolAddress((void**)&p_out1,  g_out1);
    cudaGetSymbolAddress((void**)&p_pqk,   g_pqk);
    cudaGetSymbolAddress((void**)&p_pattn, g_pattn);
    cudaGetSymbolAddress((void**)&p_xh,    g_x_hi);
    cudaGetSymbolAddress((void**)&p_xl,    g_x_lo);
    cudaGetSymbolAddress((void**)&p_wqkvh, g_wqkv_hi);
    cudaGetSymbolAddress((void**)&p_wqkvl, g_wqkv_lo);
    cudaGetSymbolAddress((void**)&p_wqkh,  g_wqk_hi);
    cudaGetSymbolAddress((void**)&p_wqkl,  g_wqk_lo);
    cudaGetSymbolAddress((void**)&p_wprojh,g_wproj_hi);
    cudaGetSymbolAddress((void**)&p_wprojl,g_wproj_lo);
    cudaGetSymbolAddress((void**)&p_wth,   g_wt_hi);
    cudaGetSymbolAddress((void**)&p_wtl,   g_wt_lo);
    cudaGetSymbolAddress((void**)&p_finh,  g_fin_hi);
    cudaGetSymbolAddress((void**)&p_finl,  g_fin_lo);

    cudaFuncSetAttribute(mma_gemm, cudaFuncAttributeMaxDynamicSharedMemorySize, SMEM_TOT);

    // splits
    {
        int n4 = (M1 * CC) / 4;
        split_kernel<<<(n4 + 255) / 256, 256>>>((const float4*)x, p_xh, p_xl, n4);
        n4 = (3 * CC * CC) / 4;
        split_kernel<<<(n4 + 255) / 256, 256>>>((const float4*)w_qkv, p_wqkvh, p_wqkvl, n4);
        n4 = (2 * CC * CC) / 4;
        split_kernel<<<(n4 + 255) / 256, 256>>>((const float4*)w_qk, p_wqkh, p_wqkl, n4);
        n4 = (CC * CC) / 4;
        split_kernel<<<(n4 + 255) / 256, 256>>>((const float4*)w_proj, p_wprojh, p_wprojl, n4);
    }

    // K1: qkv = x @ w_qkv^T  (102400 x 1152, K=384)
    mma_gemm<<<dim3(3 * CC / 128, M1 / 128), 256, SMEM_TOT>>>(
        p_xh, p_xl, p_wqkvh, p_wqkvl, nullptr, p_qkv, 3 * CC, CC);

    // K2: window attention + residual
    win_attn_kernel<<<dim3(BB * WN, NH), 256>>>(p_qkv, x, p_out1);

    // K3a: LN + GELU -> bf16 hi/lo
    ln_gelu_kernel<<<M2, 128>>>(p_out1, ln_g, ln_b, p_wth, p_wtl);

    // K3b: pqk = wintok @ w_qk^T  (2048 x 768, K=384)
    mma_gemm<<<dim3(2 * CC / 128, M2 / 128), 256, SMEM_TOT>>>(
        p_wth, p_wtl, p_wqkh, p_wqkl, nullptr, p_pqk, 2 * CC, CC);

    // K4: pooled attention softmax
    pool_attn_kernel<<<dim3(BB, NH), 256>>>(p_pqk, p_pattn);

    // K5: PSA mix + residual + rearrange -> bf16 hi/lo
    psa_kernel<<<dim3(BB * NH, WS), 224>>>(p_pattn, p_out1, p_finh, p_finl);

    // K6: out = final @ w_proj^T + b_proj  (100352 x 384, K=384)
    mma_gemm<<<dim3(CC / 128, M3 / 128), 256, SMEM_TOT>>>(
        p_finh, p_finl, p_wprojh, p_wprojl, b_proj, out, CC, CC);
}

// round 10
// speedup vs baseline: 1.5759x; 1.0441x over previous
#include <cuda_runtime.h>
#include <cuda_bf16.h>
#include <cstdint>
#include <math.h>

// ---------------- problem constants ----------------
#define BB   32
#define WN   64
#define NT   50
#define CC   384
#define NH   12
#define DD   32
#define WS   7
#define HW   3136
#define SCALE 0.17677669529663687f

#define M1 (BB*WN*NT)   // 102400
#define M2 (BB*WN)      // 2048
#define M3 (BB*HW)      // 100352

// ---------------- device scratch ----------------
__device__ float g_qkv  [(size_t)M1*3*CC];
__device__ float g_out1 [(size_t)M1*CC];
__device__ float g_pqk  [(size_t)M2*2*CC];
__device__ float g_pattn[(size_t)BB*NH*WN*WN];

__device__ __nv_bfloat16 g_x_hi[(size_t)M1*CC],  g_x_lo[(size_t)M1*CC];
__device__ __nv_bfloat16 g_wqkv_hi[3*CC*CC],     g_wqkv_lo[3*CC*CC];
__device__ __nv_bfloat16 g_wqk_hi [2*CC*CC],     g_wqk_lo [2*CC*CC];
__device__ __nv_bfloat16 g_wproj_hi[CC*CC],      g_wproj_lo[CC*CC];
__device__ __nv_bfloat16 g_wt_hi[(size_t)M2*CC], g_wt_lo[(size_t)M2*CC];
__device__ __nv_bfloat16 g_fin_hi[(size_t)M3*CC],g_fin_lo[(size_t)M3*CC];

// ---------------- PTX helpers (baseline ISA only) ----------------
__device__ __forceinline__ uint32_t smem_u32(const void* p) {
    uint32_t r;
    asm("{ .reg .u64 t; cvta.to.shared.u64 t, %1; cvt.u32.u64 %0, t; }" : "=r"(r) : "l"(p));
    return r;
}
__device__ __forceinline__ void cpa16(uint32_t s, const void* g) {
    asm volatile("cp.async.cg.shared.global [%0], [%1], 16;" :: "r"(s), "l"(g));
}
__device__ __forceinline__ void cpa_commit() {
    asm volatile("cp.async.commit_group;" ::: "memory");
}
template<int N>
__device__ __forceinline__ void cpa_wait() {
    asm volatile("cp.async.wait_group %0;" :: "n"(N) : "memory");
}
__device__ __forceinline__ void ldsm_x4(uint32_t& r0, uint32_t& r1, uint32_t& r2, uint32_t& r3,
                                        uint32_t a) {
    asm volatile("ldmatrix.sync.aligned.m8n8.x4.shared.b16 {%0,%1,%2,%3}, [%4];"
                 : "=r"(r0), "=r"(r1), "=r"(r2), "=r"(r3) : "r"(a));
}
__device__ __forceinline__ void ldsm_x2(uint32_t& r0, uint32_t& r1, uint32_t a) {
    asm volatile("ldmatrix.sync.aligned.m8n8.x2.shared.b16 {%0,%1}, [%2];"
                 : "=r"(r0), "=r"(r1) : "r"(a));
}
__device__ __forceinline__ void mma_bf16(float* d, const uint32_t* a, const uint32_t* b) {
    asm volatile(
        "mma.sync.aligned.m16n8k16.row.col.f32.bf16.bf16.f32 "
        "{%0,%1,%2,%3}, {%4,%5,%6,%7}, {%8,%9}, {%0,%1,%2,%3};"
        : "+f"(d[0]), "+f"(d[1]), "+f"(d[2]), "+f"(d[3])
        : "r"(a[0]), "r"(a[1]), "r"(a[2]), "r"(a[3]), "r"(b[0]), "r"(b[1]));
}

// ---------------- bf16 hi/lo split ----------------
__global__ void split_kernel(const float4* __restrict__ in,
                             __nv_bfloat16* __restrict__ hi,
                             __nv_bfloat16* __restrict__ lo, int n4)
{
    int i = blockIdx.x * 256 + threadIdx.x;
    if (i >= n4) return;
    float4 v = in[i];
    float xs[4] = {v.x, v.y, v.z, v.w};
    union { __nv_bfloat16 b[4]; uint2 u; } H, L;
    #pragma unroll
    for (int j = 0; j < 4; j++) {
        __nv_bfloat16 h = __float2bfloat16(xs[j]);
        H.b[j] = h;
        L.b[j] = __float2bfloat16(xs[j] - __bfloat162float(h));
    }
    *reinterpret_cast<uint2*>(hi + (size_t)i * 4) = H.u;
    *reinterpret_cast<uint2*>(lo + (size_t)i * 4) = L.u;
}

// ---------------- bf16x3 HMMA GEMM (best: 2 CTAs/SM) ----------------
#define BKH   32
#define PITCH 80
#define PLANE (128 * PITCH)
#define BUF_B (4 * PLANE)
#define SMEM_TOT (2 * BUF_B)

__device__ __forceinline__ void load_plane(uint32_t dst, const __nv_bfloat16* __restrict__ G,
                                           int row0, int k0, int K, int tid)
{
    #pragma unroll
    for (int i = 0; i < 2; i++) {
        int seg = tid + i * 256;
        int r = seg >> 2, u = seg & 3;
        cpa16(dst + r * PITCH + u * 16, G + (size_t)(row0 + r) * K + k0 + u * 8);
    }
}

__global__ void __launch_bounds__(256, 2)
mma_gemm(const __nv_bfloat16* __restrict__ Ahi, const __nv_bfloat16* __restrict__ Alo,
         const __nv_bfloat16* __restrict__ Bhi, const __nv_bfloat16* __restrict__ Blo,
         const float* __restrict__ bias, float* __restrict__ C, int N, int K)
{
    extern __shared__ __align__(128) char dsm[];
    const int tid  = threadIdx.x;
    const int lane = tid & 31;
    const int wid  = tid >> 5;
    const int wm   = wid & 1;
    const int wn   = wid >> 1;
    const int m0 = blockIdx.y * 128;
    const int n0 = blockIdx.x * 128;
    const uint32_t sb = smem_u32(dsm);

    float acc[4][4][4];
    #pragma unroll
    for (int mi = 0; mi < 4; mi++)
        #pragma unroll
        for (int ni = 0; ni < 4; ni++)
            #pragma unroll
            for (int f = 0; f < 4; f++) acc[mi][ni][f] = 0.f;

    const int NC = K / BKH;

    {
        uint32_t buf = sb;
        load_plane(buf + 0 * PLANE, Ahi, m0, 0, K, tid);
        load_plane(buf + 1 * PLANE, Alo, m0, 0, K, tid);
        load_plane(buf + 2 * PLANE, Bhi, n0, 0, K, tid);
        load_plane(buf + 3 * PLANE, Blo, n0, 0, K, tid);
        cpa_commit();
    }

    const int l16 = lane & 15;
    const uint32_t a_row = wm * 64 + l16;
    const uint32_t a_cb  = ((lane >> 4) & 1) * 16;
    const uint32_t b_row = wn * 32 + (l16 & 7);
    const uint32_t b_cb  = (l16 >> 3) * 16;

    for (int c = 0; c < NC; c++) {
        if (c + 1 < NC) {
            uint32_t buf = sb + ((c + 1) & 1) * BUF_B;
            load_plane(buf + 0 * PLANE, Ahi, m0, (c + 1) * BKH, K, tid);
            load_plane(buf + 1 * PLANE, Alo, m0, (c + 1) * BKH, K, tid);
            load_plane(buf + 2 * PLANE, Bhi, n0, (c + 1) * BKH, K, tid);
            load_plane(buf + 3 * PLANE, Blo, n0, (c + 1) * BKH, K, tid);
            cpa_commit();
            cpa_wait<1>();
        } else {
            cpa_wait<0>();
        }
        __syncthreads();

        const uint32_t buf = sb + (c & 1) * BUF_B;
        #pragma unroll
        for (int ks = 0; ks < 2; ks++) {
            uint32_t ah[4][4], al[4][4], bh[4][2], bl[4][2];
            #pragma unroll
            for (int mi = 0; mi < 4; mi++) {
                uint32_t off = (a_row + mi * 16) * PITCH + ks * 32 + a_cb;
                ldsm_x4(ah[mi][0], ah[mi][1], ah[mi][2], ah[mi][3], buf + 0 * PLANE + off);
                ldsm_x4(al[mi][0], al[mi][1], al[mi][2], al[mi][3], buf + 1 * PLANE + off);
            }
            #pragma unroll
            for (int ni = 0; ni < 4; ni++) {
                uint32_t off = (b_row + ni * 8) * PITCH + ks * 32 + b_cb;
                ldsm_x2(bh[ni][0], bh[ni][1], buf + 2 * PLANE + off);
                ldsm_x2(bl[ni][0], bl[ni][1], buf + 3 * PLANE + off);
            }
            #pragma unroll
            for (int mi = 0; mi < 4; mi++)
                #pragma unroll
                for (int ni = 0; ni < 4; ni++) {
                    mma_bf16(acc[mi][ni], ah[mi], bh[ni]);
                    mma_bf16(acc[mi][ni], ah[mi], bl[ni]);
                    mma_bf16(acc[mi][ni], al[mi], bh[ni]);
                }
        }
        __syncthreads();
    }

    const int rr = lane >> 2, cp = (lane & 3) * 2;
    #pragma unroll
    for (int mi = 0; mi < 4; mi++) {
        int row = m0 + wm * 64 + mi * 16 + rr;
        #pragma unroll
        for (int ni = 0; ni < 4; ni++) {
            int col = n0 + wn * 32 + ni * 8 + cp;
            float b0 = 0.f, b1 = 0.f;
            if (bias) { b0 = bias[col]; b1 = bias[col + 1]; }
            float* p = C + (size_t)row * N + col;
            p[0] = acc[mi][ni][0] + b0;
            p[1] = acc[mi][ni][1] + b1;
            float* q = p + (size_t)8 * N;
            q[0] = acc[mi][ni][2] + b0;
            q[1] = acc[mi][ni][3] + b1;
        }
    }
}

// ---------------- K2 v3: window attention + residual (best) -----------------
#define QP 36
#define AP 52
__global__ void __launch_bounds__(256)
win_attn_kernel(const float* __restrict__ qkv,
                const float* __restrict__ x,
                float* __restrict__ out1)
{
    const int bw = blockIdx.x;
    const int hh = blockIdx.y;
    __shared__ __align__(16) float q[NT][QP];
    __shared__ __align__(16) float k[NT][QP];
    __shared__ __align__(16) float v[NT][QP];
    __shared__ __align__(16) float at[NT][AP];
    const int tid  = threadIdx.x;
    const int warp = tid >> 5, lane = tid & 31;

    {
        const float* base = qkv + (size_t)bw * NT * (3 * CC) + hh * DD;
        for (int seg = tid; seg < NT * 24; seg += 256) {
            int i = seg / 24, r = seg % 24;
            int t = r >> 3, u = r & 7;
            float4 val = *reinterpret_cast<const float4*>(base + (size_t)i * (3 * CC) + t * CC + u * 4);
            float* dst = (t == 0 ? &q[i][u * 4] : t == 1 ? &k[i][u * 4] : &v[i][u * 4]);
            *reinterpret_cast<float4*>(dst) = val;
        }
    }
    __syncthreads();

    for (int u = tid; u < 650; u += 256) {
        const int ig = u / 50, j = u % 50;
        const int i0 = ig * 4;
        const int i1 = (i0 + 1 < NT) ? i0 + 1 : NT - 1;
        const int i2 = (i0 + 2 < NT) ? i0 + 2 : NT - 1;
        const int i3 = (i0 + 3 < NT) ? i0 + 3 : NT - 1;
        float a0 = 0.f, a1 = 0.f, a2 = 0.f, a3 = 0.f;
        #pragma unroll
        for (int d4 = 0; d4 < 8; d4++) {
            float4 kv = *reinterpret_cast<const float4*>(&k[j][d4 * 4]);
            float4 q0 = *reinterpret_cast<const float4*>(&q[i0][d4 * 4]);
            float4 q1 = *reinterpret_cast<const float4*>(&q[i1][d4 * 4]);
            float4 q2 = *reinterpret_cast<const float4*>(&q[i2][d4 * 4]);
            float4 q3 = *reinterpret_cast<const float4*>(&q[i3][d4 * 4]);
            a0 += q0.x * kv.x + q0.y * kv.y + q0.z * kv.z + q0.w * kv.w;
            a1 += q1.x * kv.x + q1.y * kv.y + q1.z * kv.z + q1.w * kv.w;
            a2 += q2.x * kv.x + q2.y * kv.y + q2.z * kv.z + q2.w * kv.w;
            a3 += q3.x * kv.x + q3.y * kv.y + q3.z * kv.z + q3.w * kv.w;
        }
        at[i0][j] = a0 * SCALE;
        if (i0 + 1 < NT) at[i0 + 1][j] = a1 * SCALE;
        if (i0 + 2 < NT) at[i0 + 2][j] = a2 * SCALE;
        if (i0 + 3 < NT) at[i0 + 3][j] = a3 * SCALE;
    }
    __syncthreads();

    for (int i = warp; i < NT; i += 8) {
        float a0 = at[i][lane];
        float a1 = (lane < 18) ? at[i][32 + lane] : -1e30f;
        float m = fmaxf(a0, a1);
        #pragma unroll
        for (int o = 16; o; o >>= 1) m = fmaxf(m, __shfl_xor_sync(0xFFFFFFFFu, m, o));
        float e0 = __expf(a0 - m);
        float e1 = (lane < 18) ? __expf(a1 - m) : 0.f;
        float s = e0 + e1;
        #pragma unroll
        for (int o = 16; o; o >>= 1) s += __shfl_xor_sync(0xFFFFFFFFu, s, o);
        float inv = 1.f / s;
        at[i][lane] = e0 * inv;
        if (lane < 18) at[i][32 + lane] = e1 * inv;
    }
    __syncthreads();

    for (int u = tid; u < 416; u += 256) {
        const int ig = u >> 5, dd = u & 31;
        const int i0 = ig * 4;
        const int i1 = (i0 + 1 < NT) ? i0 + 1 : NT - 1;
        const int i2 = (i0 + 2 < NT) ? i0 + 2 : NT - 1;
        const int i3 = (i0 + 3 < NT) ? i0 + 3 : NT - 1;
        float a0 = 0.f, a1 = 0.f, a2 = 0.f, a3 = 0.f;
        #pragma unroll
        for (int j4 = 0; j4 < 12; j4++) {
            float v0 = v[j4 * 4 + 0][dd], v1 = v[j4 * 4 + 1][dd];
            float v2 = v[j4 * 4 + 2][dd], v3 = v[j4 * 4 + 3][dd];
            float4 p0 = *reinterpret_cast<const float4*>(&at[i0][j4 * 4]);
            float4 p1 = *reinterpret_cast<const float4*>(&at[i1][j4 * 4]);
            float4 p2 = *reinterpret_cast<const float4*>(&at[i2][j4 * 4]);
            float4 p3 = *reinterpret_cast<const float4*>(&at[i3][j4 * 4]);
            a0 += p0.x * v0 + p0.y * v1 + p0.z * v2 + p0.w * v3;
            a1 += p1.x * v0 + p1.y * v1 + p1.z * v2 + p1.w * v3;
            a2 += p2.x * v0 + p2.y * v1 + p2.z * v2 + p2.w * v3;
            a3 += p3.x * v0 + p3.y * v1 + p3.z * v2 + p3.w * v3;
        }
        {
            float v0 = v[48][dd], v1 = v[49][dd];
            a0 += at[i0][48] * v0 + at[i0][49] * v1;
            a1 += at[i1][48] * v0 + at[i1][49] * v1;
            a2 += at[i2][48] * v0 + at[i2][49] * v1;
            a3 += at[i3][48] * v0 + at[i3][49] * v1;
        }
        const size_t ob = (size_t)bw * NT * CC + hh * DD + dd;
        float r[4] = {a0, a1, a2, a3};
        #pragma unroll
        for (int t = 0; t < 4; t++) {
            int i = i0 + t;
            if (i < NT) {
                size_t o = ob + (size_t)i * CC;
                out1[o] = r[t] + x[o];
            }
        }
    }
}

// ---------------- K3a: LayerNorm + exact GELU -> bf16 hi/lo -----------------
__global__ void ln_gelu_kernel(const float* __restrict__ out1,
                               const float* __restrict__ g,
                               const float* __restrict__ b,
                               __nv_bfloat16* __restrict__ wt_hi,
                               __nv_bfloat16* __restrict__ wt_lo)
{
    const int bw = blockIdx.x;
    const int tid = threadIdx.x; // 128
    const float* row = out1 + (size_t)bw * NT * CC;
    float vv[3], s = 0.f, s2 = 0.f;
    #pragma unroll
    for (int i = 0; i < 3; i++) {
        vv[i] = row[tid + i * 128];
        s += vv[i]; s2 += vv[i] * vv[i];
    }
    __shared__ float rs[4], rs2[4];
    #pragma unroll
    for (int o = 16; o; o >>= 1) {
        s  += __shfl_down_sync(0xFFFFFFFFu, s,  o);
        s2 += __shfl_down_sync(0xFFFFFFFFu, s2, o);
    }
    if ((tid & 31) == 0) { rs[tid >> 5] = s; rs2[tid >> 5] = s2; }
    __syncthreads();
    float S  = rs[0] + rs[1] + rs[2] + rs[3];
    float S2 = rs2[0] + rs2[1] + rs2[2] + rs2[3];
    float mean = S / (float)CC;
    float var  = S2 / (float)CC - mean * mean;
    float inv  = rsqrtf(var + 1e-5f);
    #pragma unroll
    for (int i = 0; i < 3; i++) {
        int c = tid + i * 128;
        float nz = (vv[i] - mean) * inv * g[c] + b[c];
        float ge = 0.5f * nz * (1.f + erff(nz * 0.70710678118654752f));
        __nv_bfloat16 h = __float2bfloat16(ge);
        wt_hi[(size_t)bw * CC + c] = h;
        wt_lo[(size_t)bw * CC + c] = __float2bfloat16(ge - __bfloat162float(h));
    }
}

// ---------------- K4: pooled attention softmax (warp-parallel) --------------
__global__ void pool_attn_kernel(const float* __restrict__ pqk,
                                 float* __restrict__ pattn)
{
    const int b = blockIdx.x, hh = blockIdx.y;
    __shared__ float pq[WN][32];
    __shared__ float pk[WN][33];
    __shared__ float sc[WN][WN];
    const int tid = threadIdx.x; // 256
    const int warp = tid >> 5, lane = tid & 31;

    for (int idx = tid; idx < WN * 32; idx += 256) {
        int w = idx >> 5, d = idx & 31;
        size_t base = (size_t)(b * WN + w) * (2 * CC) + hh * DD + d;
        pq[w][d] = pqk[base];
        pk[w][d] = pqk[base + CC];
    }
    __syncthreads();

    for (int idx = tid; idx < WN * WN; idx += 256) {
        int w = idx >> 6, vv = idx & 63;
        float s = 0.f;
        #pragma unroll
        for (int d = 0; d < 32; d++) s += pq[w][d] * pk[vv][d];
        sc[w][vv] = s * SCALE;
    }
    __syncthreads();

    // warp-parallel softmax: warp handles rows warp, warp+8, ...
    for (int i = warp; i < WN; i += 8) {
        float a0 = sc[i][lane];
        float a1 = sc[i][32 + lane];
        float m = fmaxf(a0, a1);
        #pragma unroll
        for (int o = 16; o; o >>= 1) m = fmaxf(m, __shfl_xor_sync(0xFFFFFFFFu, m, o));
        float e0 = __expf(a0 - m);
        float e1 = __expf(a1 - m);
        float s = e0 + e1;
        #pragma unroll
        for (int o = 16; o; o >>= 1) s += __shfl_xor_sync(0xFFFFFFFFu, s, o);
        float inv = 1.f / s;
        sc[i][lane] = e0 * inv;
        sc[i][32 + lane] = e1 * inv;
    }
    __syncthreads();

    float* dst = pattn + (size_t)(b * NH + hh) * WN * WN;
    for (int idx = tid; idx < WN * WN; idx += 256) dst[idx] = sc[idx >> 6][idx & 63];
}

// ---------------- K5 v3: PSA mix via (sp + I) trick -> bf16 hi/lo -----------
// Residual ax[w] equals bv[w], so fold it into the matrix: sp[w][w] += 1.
// Removes the entire second out1 read loop (-154MB traffic).
__global__ void psa_kernel(const float* __restrict__ pattn,
                           const float* __restrict__ out1,
                           __nv_bfloat16* __restrict__ fin_hi,
                           __nv_bfloat16* __restrict__ fin_lo)
{
    const int bh = blockIdx.x;
    const int b = bh / NH, hh = bh % NH;
    const int si = blockIdx.y;
    __shared__ float sp[WN][WN];
    const int tid = threadIdx.x; // 224

    const float* src = pattn + (size_t)bh * WN * WN;
    for (int idx = tid; idx < WN * WN; idx += 224) sp[idx >> 6][idx & 63] = src[idx];
    __syncthreads();
    if (tid < WN) sp[tid][tid] += 1.0f;   // fold residual into the matrix
    __syncthreads();

    const int sj = tid >> 5, dd = tid & 31;
    const int s = si * 7 + sj;
    const int col = hh * DD + dd;

    float acc[WN];
    #pragma unroll
    for (int w = 0; w < WN; w++) acc[w] = 0.f;

    for (int vv = 0; vv < WN; vv++) {
        float bv = out1[((size_t)(b * WN + vv) * NT + s + 1) * CC + col];
        #pragma unroll
        for (int w = 0; w < WN; w++) acc[w] += sp[w][vv] * bv;
    }

    for (int w = 0; w < WN; w++) {
        int hi = w >> 3, wi = w & 7;
        int y = hi * WS + si, xx = wi * WS + sj;
        size_t o = ((size_t)b * HW + y * 56 + xx) * CC + col;
        float f = acc[w];
        __nv_bfloat16 h = __float2bfloat16(f);
        fin_hi[o] = h;
        fin_lo[o] = __float2bfloat16(f - __bfloat162float(h));
    }
}

// ---------------- launch ----------------
extern "C" void kernel_launch(void* const* d_in, const int* in_sizes, int n_in,
                              void* d_out, int out_size)
{
    const float* x      = (const float*)d_in[0];
    const float* w_qkv  = (const float*)d_in[3];
    const float* w_qk   = (const float*)d_in[4];
    const float* ln_g   = (const float*)d_in[5];
    const float* ln_b   = (const float*)d_in[6];
    const float* w_proj = (const float*)d_in[7];
    const float* b_proj = (const float*)d_in[8];
    float* out = (float*)d_out;

    float *p_qkv, *p_out1, *p_pqk, *p_pattn;
    __nv_bfloat16 *p_xh, *p_xl, *p_wqkvh, *p_wqkvl, *p_wqkh, *p_wqkl,
                  *p_wprojh, *p_wprojl, *p_wth, *p_wtl, *p_finh, *p_finl;
    cudaGetSymbolAddress((void**)&p_qkv,   g_qkv);
    cudaGetSymbolAddress((void**)&p_out1,  g_out1);
    cudaGetSymbolAddress((void**)&p_pqk,   g_pqk);
    cudaGetSymbolAddress((void**)&p_pattn, g_pattn);
    cudaGetSymbolAddress((void**)&p_xh,    g_x_hi);
    cudaGetSymbolAddress((void**)&p_xl,    g_x_lo);
    cudaGetSymbolAddress((void**)&p_wqkvh, g_wqkv_hi);
    cudaGetSymbolAddress((void**)&p_wqkvl, g_wqkv_lo);
    cudaGetSymbolAddress((void**)&p_wqkh,  g_wqk_hi);
    cudaGetSymbolAddress((void**)&p_wqkl,  g_wqk_lo);
    cudaGetSymbolAddress((void**)&p_wprojh,g_wproj_hi);
    cudaGetSymbolAddress((void**)&p_wprojl,g_wproj_lo);
    cudaGetSymbolAddress((void**)&p_wth,   g_wt_hi);
    cudaGetSymbolAddress((void**)&p_wtl,   g_wt_lo);
    cudaGetSymbolAddress((void**)&p_finh,  g_fin_hi);
    cudaGetSymbolAddress((void**)&p_finl,  g_fin_lo);

    cudaFuncSetAttribute(mma_gemm, cudaFuncAttributeMaxDynamicSharedMemorySize, SMEM_TOT);

    // splits
    {
        int n4 = (M1 * CC) / 4;
        split_kernel<<<(n4 + 255) / 256, 256>>>((const float4*)x, p_xh, p_xl, n4);
        n4 = (3 * CC * CC) / 4;
        split_kernel<<<(n4 + 255) / 256, 256>>>((const float4*)w_qkv, p_wqkvh, p_wqkvl, n4);
        n4 = (2 * CC * CC) / 4;
        split_kernel<<<(n4 + 255) / 256, 256>>>((const float4*)w_qk, p_wqkh, p_wqkl, n4);
        n4 = (CC * CC) / 4;
        split_kernel<<<(n4 + 255) / 256, 256>>>((const float4*)w_proj, p_wprojh, p_wprojl, n4);
    }

    // K1: qkv = x @ w_qkv^T  (102400 x 1152, K=384)
    mma_gemm<<<dim3(3 * CC / 128, M1 / 128), 256, SMEM_TOT>>>(
        p_xh, p_xl, p_wqkvh, p_wqkvl, nullptr, p_qkv, 3 * CC, CC);

    // K2: window attention + residual
    win_attn_kernel<<<dim3(BB * WN, NH), 256>>>(p_qkv, x, p_out1);

    // K3a: LN + GELU -> bf16 hi/lo
    ln_gelu_kernel<<<M2, 128>>>(p_out1, ln_g, ln_b, p_wth, p_wtl);

    // K3b: pqk = wintok @ w_qk^T  (2048 x 768, K=384)
    mma_gemm<<<dim3(2 * CC / 128, M2 / 128), 256, SMEM_TOT>>>(
        p_wth, p_wtl, p_wqkh, p_wqkl, nullptr, p_pqk, 2 * CC, CC);

    // K4: pooled attention softmax
    pool_attn_kernel<<<dim3(BB, NH), 256>>>(p_pqk, p_pattn);

    // K5: PSA mix (+ residual via identity) + rearrange -> bf16 hi/lo
    psa_kernel<<<dim3(BB * NH, WS), 224>>>(p_pattn, p_out1, p_finh, p_finl);

    // K6: out = final @ w_proj^T + b_proj  (100352 x 384, K=384)
    mma_gemm<<<dim3(CC / 128, M3 / 128), 256, SMEM_TOT>>>(
        p_finh, p_finl, p_wprojh, p_wprojl, b_proj, out, CC, CC);
}

// round 11
// speedup vs baseline: 2.1371x; 1.3561x over previous
#include <cuda_runtime.h>
#include <cuda_fp16.h>
#include <cstdint>
#include <math.h>

// ---------------- problem constants ----------------
#define BB   32
#define WN   64
#define NT   50
#define CC   384
#define NH   12
#define DD   32
#define WS   7
#define HW   3136
#define SCALE 0.17677669529663687f

#define M1 (BB*WN*NT)   // 102400
#define M2 (BB*WN)      // 2048
#define M3 (BB*HW)      // 100352

// ---------------- device scratch ----------------
__device__ float g_qkv  [(size_t)M1*3*CC];
__device__ float g_out1 [(size_t)M1*CC];
__device__ float g_pqk  [(size_t)M2*2*CC];
__device__ float g_pattn[(size_t)BB*NH*WN*WN];

__device__ __half g_x_h   [(size_t)M1*CC];
__device__ __half g_wqkv_h[3*CC*CC];
__device__ __half g_wqk_h [2*CC*CC];
__device__ __half g_wproj_h[CC*CC];
__device__ __half g_wt_h  [(size_t)M2*CC];
__device__ __half g_fin_h [(size_t)M3*CC];

// ---------------- PTX helpers (baseline ISA only) ----------------
__device__ __forceinline__ uint32_t smem_u32(const void* p) {
    uint32_t r;
    asm("{ .reg .u64 t; cvta.to.shared.u64 t, %1; cvt.u32.u64 %0, t; }" : "=r"(r) : "l"(p));
    return r;
}
__device__ __forceinline__ void cpa16(uint32_t s, const void* g) {
    asm volatile("cp.async.cg.shared.global [%0], [%1], 16;" :: "r"(s), "l"(g));
}
__device__ __forceinline__ void cpa_commit() {
    asm volatile("cp.async.commit_group;" ::: "memory");
}
template<int N>
__device__ __forceinline__ void cpa_wait() {
    asm volatile("cp.async.wait_group %0;" :: "n"(N) : "memory");
}
__device__ __forceinline__ void ldsm_x4(uint32_t& r0, uint32_t& r1, uint32_t& r2, uint32_t& r3,
                                        uint32_t a) {
    asm volatile("ldmatrix.sync.aligned.m8n8.x4.shared.b16 {%0,%1,%2,%3}, [%4];"
                 : "=r"(r0), "=r"(r1), "=r"(r2), "=r"(r3) : "r"(a));
}
__device__ __forceinline__ void ldsm_x2(uint32_t& r0, uint32_t& r1, uint32_t a) {
    asm volatile("ldmatrix.sync.aligned.m8n8.x2.shared.b16 {%0,%1}, [%2];"
                 : "=r"(r0), "=r"(r1) : "r"(a));
}
__device__ __forceinline__ void mma_f16(float* d, const uint32_t* a, const uint32_t* b) {
    asm volatile(
        "mma.sync.aligned.m16n8k16.row.col.f32.f16.f16.f32 "
        "{%0,%1,%2,%3}, {%4,%5,%6,%7}, {%8,%9}, {%0,%1,%2,%3};"
        : "+f"(d[0]), "+f"(d[1]), "+f"(d[2]), "+f"(d[3])
        : "r"(a[0]), "r"(a[1]), "r"(a[2]), "r"(a[3]), "r"(b[0]), "r"(b[1]));
}

// ---------------- fp32 -> fp16 convert ----------------
__global__ void cvt_kernel(const float4* __restrict__ in,
                           __half* __restrict__ out, int n4)
{
    int i = blockIdx.x * 256 + threadIdx.x;
    if (i >= n4) return;
    float4 v = in[i];
    union { __half h[4]; uint2 u; } H;
    H.h[0] = __float2half_rn(v.x);
    H.h[1] = __float2half_rn(v.y);
    H.h[2] = __float2half_rn(v.z);
    H.h[3] = __float2half_rn(v.w);
    *reinterpret_cast<uint2*>(out + (size_t)i * 4) = H.u;
}

// ---------------- fp16 HMMA GEMM: C[m,n] = sum_k A[m,k]*W[n,k] (+bias) ------
// 128x128x32 CTA tile, 8 warps (2m x 4n), cp.async double buffer, 2 CTAs/SM.
// Single fp16 plane per operand (fp32 accumulate): 32 MMAs/chunk/warp.
#define BKH   32
#define PITCH 80
#define PLANE (128 * PITCH)
#define BUF_B (2 * PLANE)
#define SMEM_TOT (2 * BUF_B)   // 40960 B

__device__ __forceinline__ void load_plane(uint32_t dst, const __half* __restrict__ G,
                                           int row0, int k0, int K, int tid)
{
    #pragma unroll
    for (int i = 0; i < 2; i++) {
        int seg = tid + i * 256;          // 0..511
        int r = seg >> 2, u = seg & 3;
        cpa16(dst + r * PITCH + u * 16, G + (size_t)(row0 + r) * K + k0 + u * 8);
    }
}

__global__ void __launch_bounds__(256, 2)
mma_gemm(const __half* __restrict__ A, const __half* __restrict__ W,
         const float* __restrict__ bias, float* __restrict__ C, int N, int K)
{
    extern __shared__ __align__(128) char dsm[];
    const int tid  = threadIdx.x;
    const int lane = tid & 31;
    const int wid  = tid >> 5;
    const int wm   = wid & 1;
    const int wn   = wid >> 1;
    const int m0 = blockIdx.y * 128;
    const int n0 = blockIdx.x * 128;
    const uint32_t sb = smem_u32(dsm);

    float acc[4][4][4];
    #pragma unroll
    for (int mi = 0; mi < 4; mi++)
        #pragma unroll
        for (int ni = 0; ni < 4; ni++)
            #pragma unroll
            for (int f = 0; f < 4; f++) acc[mi][ni][f] = 0.f;

    const int NC = K / BKH;

    {
        load_plane(sb + 0 * PLANE, A, m0, 0, K, tid);
        load_plane(sb + 1 * PLANE, W, n0, 0, K, tid);
        cpa_commit();
    }

    const int l16 = lane & 15;
    const uint32_t a_row = wm * 64 + l16;
    const uint32_t a_cb  = ((lane >> 4) & 1) * 16;
    const uint32_t b_row = wn * 32 + (l16 & 7);
    const uint32_t b_cb  = (l16 >> 3) * 16;

    for (int c = 0; c < NC; c++) {
        if (c + 1 < NC) {
            uint32_t buf = sb + ((c + 1) & 1) * BUF_B;
            load_plane(buf + 0 * PLANE, A, m0, (c + 1) * BKH, K, tid);
            load_plane(buf + 1 * PLANE, W, n0, (c + 1) * BKH, K, tid);
            cpa_commit();
            cpa_wait<1>();
        } else {
            cpa_wait<0>();
        }
        __syncthreads();

        const uint32_t buf = sb + (c & 1) * BUF_B;
        #pragma unroll
        for (int ks = 0; ks < 2; ks++) {
            uint32_t a[4][4], b[4][2];
            #pragma unroll
            for (int mi = 0; mi < 4; mi++) {
                uint32_t off = (a_row + mi * 16) * PITCH + ks * 32 + a_cb;
                ldsm_x4(a[mi][0], a[mi][1], a[mi][2], a[mi][3], buf + 0 * PLANE + off);
            }
            #pragma unroll
            for (int ni = 0; ni < 4; ni++) {
                uint32_t off = (b_row + ni * 8) * PITCH + ks * 32 + b_cb;
                ldsm_x2(b[ni][0], b[ni][1], buf + 1 * PLANE + off);
            }
            #pragma unroll
            for (int mi = 0; mi < 4; mi++)
                #pragma unroll
                for (int ni = 0; ni < 4; ni++)
                    mma_f16(acc[mi][ni], a[mi], b[ni]);
        }
        __syncthreads();
    }

    const int rr = lane >> 2, cp = (lane & 3) * 2;
    #pragma unroll
    for (int mi = 0; mi < 4; mi++) {
        int row = m0 + wm * 64 + mi * 16 + rr;
        #pragma unroll
        for (int ni = 0; ni < 4; ni++) {
            int col = n0 + wn * 32 + ni * 8 + cp;
            float b0 = 0.f, b1 = 0.f;
            if (bias) { b0 = bias[col]; b1 = bias[col + 1]; }
            float* p = C + (size_t)row * N + col;
            p[0] = acc[mi][ni][0] + b0;
            p[1] = acc[mi][ni][1] + b1;
            float* q = p + (size_t)8 * N;
            q[0] = acc[mi][ni][2] + b0;
            q[1] = acc[mi][ni][3] + b1;
        }
    }
}

// ---------------- K2 v3: window attention + residual (best) -----------------
#define QP 36
#define AP 52
__global__ void __launch_bounds__(256)
win_attn_kernel(const float* __restrict__ qkv,
                const float* __restrict__ x,
                float* __restrict__ out1)
{
    const int bw = blockIdx.x;
    const int hh = blockIdx.y;
    __shared__ __align__(16) float q[NT][QP];
    __shared__ __align__(16) float k[NT][QP];
    __shared__ __align__(16) float v[NT][QP];
    __shared__ __align__(16) float at[NT][AP];
    const int tid  = threadIdx.x;
    const int warp = tid >> 5, lane = tid & 31;

    {
        const float* base = qkv + (size_t)bw * NT * (3 * CC) + hh * DD;
        for (int seg = tid; seg < NT * 24; seg += 256) {
            int i = seg / 24, r = seg % 24;
            int t = r >> 3, u = r & 7;
            float4 val = *reinterpret_cast<const float4*>(base + (size_t)i * (3 * CC) + t * CC + u * 4);
            float* dst = (t == 0 ? &q[i][u * 4] : t == 1 ? &k[i][u * 4] : &v[i][u * 4]);
            *reinterpret_cast<float4*>(dst) = val;
        }
    }
    __syncthreads();

    for (int u = tid; u < 650; u += 256) {
        const int ig = u / 50, j = u % 50;
        const int i0 = ig * 4;
        const int i1 = (i0 + 1 < NT) ? i0 + 1 : NT - 1;
        const int i2 = (i0 + 2 < NT) ? i0 + 2 : NT - 1;
        const int i3 = (i0 + 3 < NT) ? i0 + 3 : NT - 1;
        float a0 = 0.f, a1 = 0.f, a2 = 0.f, a3 = 0.f;
        #pragma unroll
        for (int d4 = 0; d4 < 8; d4++) {
            float4 kv = *reinterpret_cast<const float4*>(&k[j][d4 * 4]);
            float4 q0 = *reinterpret_cast<const float4*>(&q[i0][d4 * 4]);
            float4 q1 = *reinterpret_cast<const float4*>(&q[i1][d4 * 4]);
            float4 q2 = *reinterpret_cast<const float4*>(&q[i2][d4 * 4]);
            float4 q3 = *reinterpret_cast<const float4*>(&q[i3][d4 * 4]);
            a0 += q0.x * kv.x + q0.y * kv.y + q0.z * kv.z + q0.w * kv.w;
            a1 += q1.x * kv.x + q1.y * kv.y + q1.z * kv.z + q1.w * kv.w;
            a2 += q2.x * kv.x + q2.y * kv.y + q2.z * kv.z + q2.w * kv.w;
            a3 += q3.x * kv.x + q3.y * kv.y + q3.z * kv.z + q3.w * kv.w;
        }
        at[i0][j] = a0 * SCALE;
        if (i0 + 1 < NT) at[i0 + 1][j] = a1 * SCALE;
        if (i0 + 2 < NT) at[i0 + 2][j] = a2 * SCALE;
        if (i0 + 3 < NT) at[i0 + 3][j] = a3 * SCALE;
    }
    __syncthreads();

    for (int i = warp; i < NT; i += 8) {
        float a0 = at[i][lane];
        float a1 = (lane < 18) ? at[i][32 + lane] : -1e30f;
        float m = fmaxf(a0, a1);
        #pragma unroll
        for (int o = 16; o; o >>= 1) m = fmaxf(m, __shfl_xor_sync(0xFFFFFFFFu, m, o));
        float e0 = __expf(a0 - m);
        float e1 = (lane < 18) ? __expf(a1 - m) : 0.f;
        float s = e0 + e1;
        #pragma unroll
        for (int o = 16; o; o >>= 1) s += __shfl_xor_sync(0xFFFFFFFFu, s, o);
        float inv = 1.f / s;
        at[i][lane] = e0 * inv;
        if (lane < 18) at[i][32 + lane] = e1 * inv;
    }
    __syncthreads();

    for (int u = tid; u < 416; u += 256) {
        const int ig = u >> 5, dd = u & 31;
        const int i0 = ig * 4;
        const int i1 = (i0 + 1 < NT) ? i0 + 1 : NT - 1;
        const int i2 = (i0 + 2 < NT) ? i0 + 2 : NT - 1;
        const int i3 = (i0 + 3 < NT) ? i0 + 3 : NT - 1;
        float a0 = 0.f, a1 = 0.f, a2 = 0.f, a3 = 0.f;
        #pragma unroll
        for (int j4 = 0; j4 < 12; j4++) {
            float v0 = v[j4 * 4 + 0][dd], v1 = v[j4 * 4 + 1][dd];
            float v2 = v[j4 * 4 + 2][dd], v3 = v[j4 * 4 + 3][dd];
            float4 p0 = *reinterpret_cast<const float4*>(&at[i0][j4 * 4]);
            float4 p1 = *reinterpret_cast<const float4*>(&at[i1][j4 * 4]);
            float4 p2 = *reinterpret_cast<const float4*>(&at[i2][j4 * 4]);
            float4 p3 = *reinterpret_cast<const float4*>(&at[i3][j4 * 4]);
            a0 += p0.x * v0 + p0.y * v1 + p0.z * v2 + p0.w * v3;
            a1 += p1.x * v0 + p1.y * v1 + p1.z * v2 + p1.w * v3;
            a2 += p2.x * v0 + p2.y * v1 + p2.z * v2 + p2.w * v3;
            a3 += p3.x * v0 + p3.y * v1 + p3.z * v2 + p3.w * v3;
        }
        {
            float v0 = v[48][dd], v1 = v[49][dd];
            a0 += at[i0][48] * v0 + at[i0][49] * v1;
            a1 += at[i1][48] * v0 + at[i1][49] * v1;
            a2 += at[i2][48] * v0 + at[i2][49] * v1;
            a3 += at[i3][48] * v0 + at[i3][49] * v1;
        }
        const size_t ob = (size_t)bw * NT * CC + hh * DD + dd;
        float r[4] = {a0, a1, a2, a3};
        #pragma unroll
        for (int t = 0; t < 4; t++) {
            int i = i0 + t;
            if (i < NT) {
                size_t o = ob + (size_t)i * CC;
                out1[o] = r[t] + x[o];
            }
        }
    }
}

// ---------------- K3a: LayerNorm + exact GELU -> fp16 -----------------------
__global__ void ln_gelu_kernel(const float* __restrict__ out1,
                               const float* __restrict__ g,
                               const float* __restrict__ b,
                               __half* __restrict__ wt_h)
{
    const int bw = blockIdx.x;
    const int tid = threadIdx.x; // 128
    const float* row = out1 + (size_t)bw * NT * CC;
    float vv[3], s = 0.f, s2 = 0.f;
    #pragma unroll
    for (int i = 0; i < 3; i++) {
        vv[i] = row[tid + i * 128];
        s += vv[i]; s2 += vv[i] * vv[i];
    }
    __shared__ float rs[4], rs2[4];
    #pragma unroll
    for (int o = 16; o; o >>= 1) {
        s  += __shfl_down_sync(0xFFFFFFFFu, s,  o);
        s2 += __shfl_down_sync(0xFFFFFFFFu, s2, o);
    }
    if ((tid & 31) == 0) { rs[tid >> 5] = s; rs2[tid >> 5] = s2; }
    __syncthreads();
    float S  = rs[0] + rs[1] + rs[2] + rs[3];
    float S2 = rs2[0] + rs2[1] + rs2[2] + rs2[3];
    float mean = S / (float)CC;
    float var  = S2 / (float)CC - mean * mean;
    float inv  = rsqrtf(var + 1e-5f);
    #pragma unroll
    for (int i = 0; i < 3; i++) {
        int c = tid + i * 128;
        float nz = (vv[i] - mean) * inv * g[c] + b[c];
        float ge = 0.5f * nz * (1.f + erff(nz * 0.70710678118654752f));
        wt_h[(size_t)bw * CC + c] = __float2half_rn(ge);
    }
}

// ---------------- K4: pooled attention softmax (warp-parallel) --------------
__global__ void pool_attn_kernel(const float* __restrict__ pqk,
                                 float* __restrict__ pattn)
{
    const int b = blockIdx.x, hh = blockIdx.y;
    __shared__ float pq[WN][32];
    __shared__ float pk[WN][33];
    __shared__ float sc[WN][WN];
    const int tid = threadIdx.x; // 256
    const int warp = tid >> 5, lane = tid & 31;

    for (int idx = tid; idx < WN * 32; idx += 256) {
        int w = idx >> 5, d = idx & 31;
        size_t base = (size_t)(b * WN + w) * (2 * CC) + hh * DD + d;
        pq[w][d] = pqk[base];
        pk[w][d] = pqk[base + CC];
    }
    __syncthreads();

    for (int idx = tid; idx < WN * WN; idx += 256) {
        int w = idx >> 6, vv = idx & 63;
        float s = 0.f;
        #pragma unroll
        for (int d = 0; d < 32; d++) s += pq[w][d] * pk[vv][d];
        sc[w][vv] = s * SCALE;
    }
    __syncthreads();

    for (int i = warp; i < WN; i += 8) {
        float a0 = sc[i][lane];
        float a1 = sc[i][32 + lane];
        float m = fmaxf(a0, a1);
        #pragma unroll
        for (int o = 16; o; o >>= 1) m = fmaxf(m, __shfl_xor_sync(0xFFFFFFFFu, m, o));
        float e0 = __expf(a0 - m);
        float e1 = __expf(a1 - m);
        float s = e0 + e1;
        #pragma unroll
        for (int o = 16; o; o >>= 1) s += __shfl_xor_sync(0xFFFFFFFFu, s, o);
        float inv = 1.f / s;
        sc[i][lane] = e0 * inv;
        sc[i][32 + lane] = e1 * inv;
    }
    __syncthreads();

    float* dst = pattn + (size_t)(b * NH + hh) * WN * WN;
    for (int idx = tid; idx < WN * WN; idx += 256) dst[idx] = sc[idx >> 6][idx & 63];
}

// ---------------- K5 v3: PSA mix via (sp + I) trick -> fp16 -----------------
__global__ void psa_kernel(const float* __restrict__ pattn,
                           const float* __restrict__ out1,
                           __half* __restrict__ fin_h)
{
    const int bh = blockIdx.x;
    const int b = bh / NH, hh = bh % NH;
    const int si = blockIdx.y;
    __shared__ float sp[WN][WN];
    const int tid = threadIdx.x; // 224

    const float* src = pattn + (size_t)bh * WN * WN;
    for (int idx = tid; idx < WN * WN; idx += 224) sp[idx >> 6][idx & 63] = src[idx];
    __syncthreads();
    if (tid < WN) sp[tid][tid] += 1.0f;   // fold residual into the matrix
    __syncthreads();

    const int sj = tid >> 5, dd = tid & 31;
    const int s = si * 7 + sj;
    const int col = hh * DD + dd;

    float acc[WN];
    #pragma unroll
    for (int w = 0; w < WN; w++) acc[w] = 0.f;

    for (int vv = 0; vv < WN; vv++) {
        float bv = out1[((size_t)(b * WN + vv) * NT + s + 1) * CC + col];
        #pragma unroll
        for (int w = 0; w < WN; w++) acc[w] += sp[w][vv] * bv;
    }

    for (int w = 0; w < WN; w++) {
        int hi = w >> 3, wi = w & 7;
        int y = hi * WS + si, xx = wi * WS + sj;
        size_t o = ((size_t)b * HW + y * 56 + xx) * CC + col;
        fin_h[o] = __float2half_rn(acc[w]);
    }
}

// ---------------- launch ----------------
extern "C" void kernel_launch(void* const* d_in, const int* in_sizes, int n_in,
                              void* d_out, int out_size)
{
    const float* x      = (const float*)d_in[0];
    const float* w_qkv  = (const float*)d_in[3];
    const float* w_qk   = (const float*)d_in[4];
    const float* ln_g   = (const float*)d_in[5];
    const float* ln_b   = (const float*)d_in[6];
    const float* w_proj = (const float*)d_in[7];
    const float* b_proj = (const float*)d_in[8];
    float* out = (float*)d_out;

    float *p_qkv, *p_out1, *p_pqk, *p_pattn;
    __half *p_xh, *p_wqkvh, *p_wqkh, *p_wprojh, *p_wth, *p_finh;
    cudaGetSymbolAddress((void**)&p_qkv,   g_qkv);
    cudaGetSymbolAddress((void**)&p_out1,  g_out1);
    cudaGetSymbolAddress((void**)&p_pqk,   g_pqk);
    cudaGetSymbolAddress((void**)&p_pattn, g_pattn);
    cudaGetSymbolAddress((void**)&p_xh,    g_x_h);
    cudaGetSymbolAddress((void**)&p_wqkvh, g_wqkv_h);
    cudaGetSymbolAddress((void**)&p_wqkh,  g_wqk_h);
    cudaGetSymbolAddress((void**)&p_wprojh,g_wproj_h);
    cudaGetSymbolAddress((void**)&p_wth,   g_wt_h);
    cudaGetSymbolAddress((void**)&p_finh,  g_fin_h);

    cudaFuncSetAttribute(mma_gemm, cudaFuncAttributeMaxDynamicSharedMemorySize, SMEM_TOT);

    // fp32 -> fp16 converts
    {
        int n4 = (M1 * CC) / 4;
        cvt_kernel<<<(n4 + 255) / 256, 256>>>((const float4*)x, p_xh, n4);
        n4 = (3 * CC * CC) / 4;
        cvt_kernel<<<(n4 + 255) / 256, 256>>>((const float4*)w_qkv, p_wqkvh, n4);
        n4 = (2 * CC * CC) / 4;
        cvt_kernel<<<(n4 + 255) / 256, 256>>>((const float4*)w_qk, p_wqkh, n4);
        n4 = (CC * CC) / 4;
        cvt_kernel<<<(n4 + 255) / 256, 256>>>((const float4*)w_proj, p_wprojh, n4);
    }

    // K1: qkv = x @ w_qkv^T  (102400 x 1152, K=384)
    mma_gemm<<<dim3(3 * CC / 128, M1 / 128), 256, SMEM_TOT>>>(
        p_xh, p_wqkvh, nullptr, p_qkv, 3 * CC, CC);

    // K2: window attention + residual
    win_attn_kernel<<<dim3(BB * WN, NH), 256>>>(p_qkv, x, p_out1);

    // K3a: LN + GELU -> fp16
    ln_gelu_kernel<<<M2, 128>>>(p_out1, ln_g, ln_b, p_wth);

    // K3b: pqk = wintok @ w_qk^T  (2048 x 768, K=384)
    mma_gemm<<<dim3(2 * CC / 128, M2 / 128), 256, SMEM_TOT>>>(
        p_wth, p_wqkh, nullptr, p_pqk, 2 * CC, CC);

    // K4: pooled attention softmax
    pool_attn_kernel<<<dim3(BB, NH), 256>>>(p_pqk, p_pattn);

    // K5: PSA mix (+ residual via identity) + rearrange -> fp16
    psa_kernel<<<dim3(BB * NH, WS), 224>>>(p_pattn, p_out1, p_finh);

    // K6: out = final @ w_proj^T + b_proj  (100352 x 384, K=384)
    mma_gemm<<<dim3(CC / 128, M3 / 128), 256, SMEM_TOT>>>(
        p_finh, p_wprojh, b_proj, out, CC, CC);
}

// round 14
// speedup vs baseline: 2.3979x; 1.1220x over previous
#include <cuda_runtime.h>
#include <cuda_fp16.h>
#include <cstdint>
#include <math.h>

// ---------------- problem constants ----------------
#define BB   32
#define WN   64
#define NT   50
#define CC   384
#define NH   12
#define DD   32
#define WS   7
#define HW   3136
#define SCALE 0.17677669529663687f

#define M1 (BB*WN*NT)   // 102400
#define M2 (BB*WN)      // 2048
#define M3 (BB*HW)      // 100352

// ---------------- device scratch ----------------
__device__ __half g_qkv_h[(size_t)M1*3*CC];     // fp16 qkv (236 MB)
__device__ float g_out1 [(size_t)M1*CC];
__device__ float g_pqk  [(size_t)M2*2*CC];
__device__ float g_pattn[(size_t)BB*NH*WN*WN];

__device__ __half g_x_h   [(size_t)M1*CC];
__device__ __half g_wqkv_h[3*CC*CC];
__device__ __half g_wqk_h [2*CC*CC];
__device__ __half g_wproj_h[CC*CC];
__device__ __half g_wt_h  [(size_t)M2*CC];
__device__ __half g_fin_h [(size_t)M3*CC];

// ---------------- PTX helpers (baseline ISA only) ----------------
__device__ __forceinline__ uint32_t smem_u32(const void* p) {
    uint32_t r;
    asm("{ .reg .u64 t; cvta.to.shared.u64 t, %1; cvt.u32.u64 %0, t; }" : "=r"(r) : "l"(p));
    return r;
}
__device__ __forceinline__ void cpa16(uint32_t s, const void* g) {
    asm volatile("cp.async.cg.shared.global [%0], [%1], 16;" :: "r"(s), "l"(g));
}
__device__ __forceinline__ void cpa_commit() {
    asm volatile("cp.async.commit_group;" ::: "memory");
}
template<int N>
__device__ __forceinline__ void cpa_wait() {
    asm volatile("cp.async.wait_group %0;" :: "n"(N) : "memory");
}
__device__ __forceinline__ void ldsm_x4(uint32_t& r0, uint32_t& r1, uint32_t& r2, uint32_t& r3,
                                        uint32_t a) {
    asm volatile("ldmatrix.sync.aligned.m8n8.x4.shared.b16 {%0,%1,%2,%3}, [%4];"
                 : "=r"(r0), "=r"(r1), "=r"(r2), "=r"(r3) : "r"(a));
}
__device__ __forceinline__ void ldsm_x2(uint32_t& r0, uint32_t& r1, uint32_t a) {
    asm volatile("ldmatrix.sync.aligned.m8n8.x2.shared.b16 {%0,%1}, [%2];"
                 : "=r"(r0), "=r"(r1) : "r"(a));
}
__device__ __forceinline__ void mma_f16(float* d, const uint32_t* a, const uint32_t* b) {
    asm volatile(
        "mma.sync.aligned.m16n8k16.row.col.f32.f16.f16.f32 "
        "{%0,%1,%2,%3}, {%4,%5,%6,%7}, {%8,%9}, {%0,%1,%2,%3};"
        : "+f"(d[0]), "+f"(d[1]), "+f"(d[2]), "+f"(d[3])
        : "r"(a[0]), "r"(a[1]), "r"(a[2]), "r"(a[3]), "r"(b[0]), "r"(b[1]));
}

// ---------------- fp32 -> fp16 convert ----------------
__global__ void cvt_kernel(const float4* __restrict__ in,
                           __half* __restrict__ out, int n4)
{
    int i = blockIdx.x * 256 + threadIdx.x;
    if (i >= n4) return;
    float4 v = in[i];
    union { __half h[4]; uint2 u; } H;
    H.h[0] = __float2half_rn(v.x);
    H.h[1] = __float2half_rn(v.y);
    H.h[2] = __float2half_rn(v.z);
    H.h[3] = __float2half_rn(v.w);
    *reinterpret_cast<uint2*>(out + (size_t)i * 4) = H.u;
}

// ---------------- fp16 HMMA GEMM: C[m,n] = sum_k A[m,k]*W[n,k] (+bias) ------
// 128x128x64 CTA tile, 8 warps (2m x 4n), cp.async double buffer, 2 CTAs/SM.
// PITCH 144 B: 8 consecutive ldsm rows hit disjoint 16B bank groups.
// Optional fp16 output plane (Ch) for qkv.
#define BKH   64
#define PITCH 144
#define PLANE (128 * PITCH)        // 18432 B
#define BUF_B (2 * PLANE)          // 36864 B
#define SMEM_TOT (2 * BUF_B)       // 73728 B

__device__ __forceinline__ void load_plane(uint32_t dst, const __half* __restrict__ G,
                                           int row0, int k0, int K, int tid)
{
    #pragma unroll
    for (int i = 0; i < 4; i++) {
        int seg = tid + i * 256;       // 0..1023
        int r = seg >> 3, u = seg & 7;
        cpa16(dst + r * PITCH + u * 16, G + (size_t)(row0 + r) * K + k0 + u * 8);
    }
}

__global__ void __launch_bounds__(256, 2)
mma_gemm(const __half* __restrict__ A, const __half* __restrict__ W,
         const float* __restrict__ bias, float* __restrict__ C,
         __half* __restrict__ Ch, int N, int K)
{
    extern __shared__ __align__(128) char dsm[];
    const int tid  = threadIdx.x;
    const int lane = tid & 31;
    const int wid  = tid >> 5;
    const int wm   = wid & 1;
    const int wn   = wid >> 1;
    const int m0 = blockIdx.y * 128;
    const int n0 = blockIdx.x * 128;
    const uint32_t sb = smem_u32(dsm);

    float acc[4][4][4];
    #pragma unroll
    for (int mi = 0; mi < 4; mi++)
        #pragma unroll
        for (int ni = 0; ni < 4; ni++)
            #pragma unroll
            for (int f = 0; f < 4; f++) acc[mi][ni][f] = 0.f;

    const int NC = K / BKH;            // 6

    {
        load_plane(sb + 0 * PLANE, A, m0, 0, K, tid);
        load_plane(sb + 1 * PLANE, W, n0, 0, K, tid);
        cpa_commit();
    }

    const int l16 = lane & 15;
    const uint32_t a_row = wm * 64 + l16;
    const uint32_t a_cb  = ((lane >> 4) & 1) * 16;
    const uint32_t b_row = wn * 32 + (l16 & 7);
    const uint32_t b_cb  = (l16 >> 3) * 16;

    for (int c = 0; c < NC; c++) {
        if (c + 1 < NC) {
            uint32_t buf = sb + ((c + 1) & 1) * BUF_B;
            load_plane(buf + 0 * PLANE, A, m0, (c + 1) * BKH, K, tid);
            load_plane(buf + 1 * PLANE, W, n0, (c + 1) * BKH, K, tid);
            cpa_commit();
            cpa_wait<1>();
        } else {
            cpa_wait<0>();
        }
        __syncthreads();

        const uint32_t buf = sb + (c & 1) * BUF_B;
        #pragma unroll
        for (int ks = 0; ks < 4; ks++) {       // 4 x k16 per 64-chunk
            uint32_t a[4][4], b[4][2];
            #pragma unroll
            for (int mi = 0; mi < 4; mi++) {
                uint32_t off = (a_row + mi * 16) * PITCH + ks * 32 + a_cb;
                ldsm_x4(a[mi][0], a[mi][1], a[mi][2], a[mi][3], buf + 0 * PLANE + off);
            }
            #pragma unroll
            for (int ni = 0; ni < 4; ni++) {
                uint32_t off = (b_row + ni * 8) * PITCH + ks * 32 + b_cb;
                ldsm_x2(b[ni][0], b[ni][1], buf + 1 * PLANE + off);
            }
            #pragma unroll
            for (int mi = 0; mi < 4; mi++)
                #pragma unroll
                for (int ni = 0; ni < 4; ni++)
                    mma_f16(acc[mi][ni], a[mi], b[ni]);
        }
        __syncthreads();
    }

    const int rr = lane >> 2, cp = (lane & 3) * 2;
    if (Ch) {
        #pragma unroll
        for (int mi = 0; mi < 4; mi++) {
            int row = m0 + wm * 64 + mi * 16 + rr;
            #pragma unroll
            for (int ni = 0; ni < 4; ni++) {
                int col = n0 + wn * 32 + ni * 8 + cp;
                __half2* p = reinterpret_cast<__half2*>(Ch + (size_t)row * N + col);
                *p = __floats2half2_rn(acc[mi][ni][0], acc[mi][ni][1]);
                __half2* q = reinterpret_cast<__half2*>(Ch + (size_t)(row + 8) * N + col);
                *q = __floats2half2_rn(acc[mi][ni][2], acc[mi][ni][3]);
            }
        }
    } else {
        #pragma unroll
        for (int mi = 0; mi < 4; mi++) {
            int row = m0 + wm * 64 + mi * 16 + rr;
            #pragma unroll
            for (int ni = 0; ni < 4; ni++) {
                int col = n0 + wn * 32 + ni * 8 + cp;
                float b0 = 0.f, b1 = 0.f;
                if (bias) { b0 = bias[col]; b1 = bias[col + 1]; }
                float* p = C + (size_t)row * N + col;
                p[0] = acc[mi][ni][0] + b0;
                p[1] = acc[mi][ni][1] + b1;
                float* q = p + (size_t)8 * N;
                q[0] = acc[mi][ni][2] + b0;
                q[1] = acc[mi][ni][3] + b1;
            }
        }
    }
}

// ---------------- K2: window attention + residual (fp16 qkv input) ----------
#define QP 36
#define AP 52
__global__ void __launch_bounds__(256)
win_attn_kernel(const __half* __restrict__ qkv,
                const float* __restrict__ x,
                float* __restrict__ out1)
{
    const int bw = blockIdx.x;
    const int hh = blockIdx.y;
    __shared__ __align__(16) float q[NT][QP];
    __shared__ __align__(16) float k[NT][QP];
    __shared__ __align__(16) float v[NT][QP];
    __shared__ __align__(16) float at[NT][AP];
    const int tid  = threadIdx.x;
    const int warp = tid >> 5, lane = tid & 31;

    // load q,k,v: 32 halves per row per tensor = FOUR 16B (8-half) segments
    {
        const __half* base = qkv + (size_t)bw * NT * (3 * CC) + hh * DD;
        for (int seg = tid; seg < NT * 12; seg += 256) {
            int i = seg / 12, r = seg % 12;
            int t = r >> 2, u = r & 3;    // tensor 0..2, 16B chunk 0..3
            const __half* p = base + (size_t)i * (3 * CC) + t * CC + u * 8;
            union { uint4 raw; __half2 h2[4]; } U;
            U.raw = *reinterpret_cast<const uint4*>(p);
            float* dst = (t == 0 ? &q[i][u * 8] : t == 1 ? &k[i][u * 8] : &v[i][u * 8]);
            #pragma unroll
            for (int j = 0; j < 4; j++) {
                float2 f = __half22float2(U.h2[j]);
                dst[j * 2] = f.x; dst[j * 2 + 1] = f.y;
            }
        }
    }
    __syncthreads();

    for (int u = tid; u < 650; u += 256) {
        const int ig = u / 50, j = u % 50;
        const int i0 = ig * 4;
        const int i1 = (i0 + 1 < NT) ? i0 + 1 : NT - 1;
        const int i2 = (i0 + 2 < NT) ? i0 + 2 : NT - 1;
        const int i3 = (i0 + 3 < NT) ? i0 + 3 : NT - 1;
        float a0 = 0.f, a1 = 0.f, a2 = 0.f, a3 = 0.f;
        #pragma unroll
        for (int d4 = 0; d4 < 8; d4++) {
            float4 kv = *reinterpret_cast<const float4*>(&k[j][d4 * 4]);
            float4 q0 = *reinterpret_cast<const float4*>(&q[i0][d4 * 4]);
            float4 q1 = *reinterpret_cast<const float4*>(&q[i1][d4 * 4]);
            float4 q2 = *reinterpret_cast<const float4*>(&q[i2][d4 * 4]);
            float4 q3 = *reinterpret_cast<const float4*>(&q[i3][d4 * 4]);
            a0 += q0.x * kv.x + q0.y * kv.y + q0.z * kv.z + q0.w * kv.w;
            a1 += q1.x * kv.x + q1.y * kv.y + q1.z * kv.z + q1.w * kv.w;
            a2 += q2.x * kv.x + q2.y * kv.y + q2.z * kv.z + q2.w * kv.w;
            a3 += q3.x * kv.x + q3.y * kv.y + q3.z * kv.z + q3.w * kv.w;
        }
        at[i0][j] = a0 * SCALE;
        if (i0 + 1 < NT) at[i0 + 1][j] = a1 * SCALE;
        if (i0 + 2 < NT) at[i0 + 2][j] = a2 * SCALE;
        if (i0 + 3 < NT) at[i0 + 3][j] = a3 * SCALE;
    }
    __syncthreads();

    for (int i = warp; i < NT; i += 8) {
        float a0 = at[i][lane];
        float a1 = (lane < 18) ? at[i][32 + lane] : -1e30f;
        float m = fmaxf(a0, a1);
        #pragma unroll
        for (int o = 16; o; o >>= 1) m = fmaxf(m, __shfl_xor_sync(0xFFFFFFFFu, m, o));
        float e0 = __expf(a0 - m);
        float e1 = (lane < 18) ? __expf(a1 - m) : 0.f;
        float s = e0 + e1;
        #pragma unroll
        for (int o = 16; o; o >>= 1) s += __shfl_xor_sync(0xFFFFFFFFu, s, o);
        float inv = 1.f / s;
        at[i][lane] = e0 * inv;
        if (lane < 18) at[i][32 + lane] = e1 * inv;
    }
    __syncthreads();

    for (int u = tid; u < 416; u += 256) {
        const int ig = u >> 5, dd = u & 31;
        const int i0 = ig * 4;
        const int i1 = (i0 + 1 < NT) ? i0 + 1 : NT - 1;
        const int i2 = (i0 + 2 < NT) ? i0 + 2 : NT - 1;
        const int i3 = (i0 + 3 < NT) ? i0 + 3 : NT - 1;
        float a0 = 0.f, a1 = 0.f, a2 = 0.f, a3 = 0.f;
        #pragma unroll
        for (int j4 = 0; j4 < 12; j4++) {
            float v0 = v[j4 * 4 + 0][dd], v1 = v[j4 * 4 + 1][dd];
            float v2 = v[j4 * 4 + 2][dd], v3 = v[j4 * 4 + 3][dd];
            float4 p0 = *reinterpret_cast<const float4*>(&at[i0][j4 * 4]);
            float4 p1 = *reinterpret_cast<const float4*>(&at[i1][j4 * 4]);
            float4 p2 = *reinterpret_cast<const float4*>(&at[i2][j4 * 4]);
            float4 p3 = *reinterpret_cast<const float4*>(&at[i3][j4 * 4]);
            a0 += p0.x * v0 + p0.y * v1 + p0.z * v2 + p0.w * v3;
            a1 += p1.x * v0 + p1.y * v1 + p1.z * v2 + p1.w * v3;
            a2 += p2.x * v0 + p2.y * v1 + p2.z * v2 + p2.w * v3;
            a3 += p3.x * v0 + p3.y * v1 + p3.z * v2 + p3.w * v3;
        }
        {
            float v0 = v[48][dd], v1 = v[49][dd];
            a0 += at[i0][48] * v0 + at[i0][49] * v1;
            a1 += at[i1][48] * v0 + at[i1][49] * v1;
            a2 += at[i2][48] * v0 + at[i2][49] * v1;
            a3 += at[i3][48] * v0 + at[i3][49] * v1;
        }
        const size_t ob = (size_t)bw * NT * CC + hh * DD + dd;
        float r[4] = {a0, a1, a2, a3};
        #pragma unroll
        for (int t = 0; t < 4; t++) {
            int i = i0 + t;
            if (i < NT) {
                size_t o = ob + (size_t)i * CC;
                out1[o] = r[t] + x[o];
            }
        }
    }
}

// ---------------- K3a: LayerNorm + exact GELU -> fp16 -----------------------
__global__ void ln_gelu_kernel(const float* __restrict__ out1,
                               const float* __restrict__ g,
                               const float* __restrict__ b,
                               __half* __restrict__ wt_h)
{
    const int bw = blockIdx.x;
    const int tid = threadIdx.x; // 128
    const float* row = out1 + (size_t)bw * NT * CC;
    float vv[3], s = 0.f, s2 = 0.f;
    #pragma unroll
    for (int i = 0; i < 3; i++) {
        vv[i] = row[tid + i * 128];
        s += vv[i]; s2 += vv[i] * vv[i];
    }
    __shared__ float rs[4], rs2[4];
    #pragma unroll
    for (int o = 16; o; o >>= 1) {
        s  += __shfl_down_sync(0xFFFFFFFFu, s,  o);
        s2 += __shfl_down_sync(0xFFFFFFFFu, s2, o);
    }
    if ((tid & 31) == 0) { rs[tid >> 5] = s; rs2[tid >> 5] = s2; }
    __syncthreads();
    float S  = rs[0] + rs[1] + rs[2] + rs[3];
    float S2 = rs2[0] + rs2[1] + rs2[2] + rs2[3];
    float mean = S / (float)CC;
    float var  = S2 / (float)CC - mean * mean;
    float inv  = rsqrtf(var + 1e-5f);
    #pragma unroll
    for (int i = 0; i < 3; i++) {
        int c = tid + i * 128;
        float nz = (vv[i] - mean) * inv * g[c] + b[c];
        float ge = 0.5f * nz * (1.f + erff(nz * 0.70710678118654752f));
        wt_h[(size_t)bw * CC + c] = __float2half_rn(ge);
    }
}

// ---------------- K4: pooled attention softmax (warp-parallel) --------------
__global__ void pool_attn_kernel(const float* __restrict__ pqk,
                                 float* __restrict__ pattn)
{
    const int b = blockIdx.x, hh = blockIdx.y;
    __shared__ float pq[WN][32];
    __shared__ float pk[WN][33];
    __shared__ float sc[WN][WN];
    const int tid = threadIdx.x; // 256
    const int warp = tid >> 5, lane = tid & 31;

    for (int idx = tid; idx < WN * 32; idx += 256) {
        int w = idx >> 5, d = idx & 31;
        size_t base = (size_t)(b * WN + w) * (2 * CC) + hh * DD + d;
        pq[w][d] = pqk[base];
        pk[w][d] = pqk[base + CC];
    }
    __syncthreads();

    for (int idx = tid; idx < WN * WN; idx += 256) {
        int w = idx >> 6, vv = idx & 63;
        float s = 0.f;
        #pragma unroll
        for (int d = 0; d < 32; d++) s += pq[w][d] * pk[vv][d];
        sc[w][vv] = s * SCALE;
    }
    __syncthreads();

    for (int i = warp; i < WN; i += 8) {
        float a0 = sc[i][lane];
        float a1 = sc[i][32 + lane];
        float m = fmaxf(a0, a1);
        #pragma unroll
        for (int o = 16; o; o >>= 1) m = fmaxf(m, __shfl_xor_sync(0xFFFFFFFFu, m, o));
        float e0 = __expf(a0 - m);
        float e1 = __expf(a1 - m);
        float s = e0 + e1;
        #pragma unroll
        for (int o = 16; o; o >>= 1) s += __shfl_xor_sync(0xFFFFFFFFu, s, o);
        float inv = 1.f / s;
        sc[i][lane] = e0 * inv;
        sc[i][32 + lane] = e1 * inv;
    }
    __syncthreads();

    float* dst = pattn + (size_t)(b * NH + hh) * WN * WN;
    for (int idx = tid; idx < WN * WN; idx += 256) dst[idx] = sc[idx >> 6][idx & 63];
}

// ---------------- K5: PSA mix via (sp + I) trick -> fp16 --------------------
__global__ void psa_kernel(const float* __restrict__ pattn,
                           const float* __restrict__ out1,
                           __half* __restrict__ fin_h)
{
    const int bh = blockIdx.x;
    const int b = bh / NH, hh = bh % NH;
    const int si = blockIdx.y;
    __shared__ float sp[WN][WN];
    const int tid = threadIdx.x; // 224

    const float* src = pattn + (size_t)bh * WN * WN;
    for (int idx = tid; idx < WN * WN; idx += 224) sp[idx >> 6][idx & 63] = src[idx];
    __syncthreads();
    if (tid < WN) sp[tid][tid] += 1.0f;
    __syncthreads();

    const int sj = tid >> 5, dd = tid & 31;
    const int s = si * 7 + sj;
    const int col = hh * DD + dd;

    float acc[WN];
    #pragma unroll
    for (int w = 0; w < WN; w++) acc[w] = 0.f;

    for (int vv = 0; vv < WN; vv++) {
        float bv = out1[((size_t)(b * WN + vv) * NT + s + 1) * CC + col];
        #pragma unroll
        for (int w = 0; w < WN; w++) acc[w] += sp[w][vv] * bv;
    }

    for (int w = 0; w < WN; w++) {
        int hi = w >> 3, wi = w & 7;
        int y = hi * WS + si, xx = wi * WS + sj;
        size_t o = ((size_t)b * HW + y * 56 + xx) * CC + col;
        fin_h[o] = __float2half_rn(acc[w]);
    }
}

// ---------------- launch ----------------
extern "C" void kernel_launch(void* const* d_in, const int* in_sizes, int n_in,
                              void* d_out, int out_size)
{
    const float* x      = (const float*)d_in[0];
    const float* w_qkv  = (const float*)d_in[3];
    const float* w_qk   = (const float*)d_in[4];
    const float* ln_g   = (const float*)d_in[5];
    const float* ln_b   = (const float*)d_in[6];
    const float* w_proj = (const float*)d_in[7];
    const float* b_proj = (const float*)d_in[8];
    float* out = (float*)d_out;

    float *p_out1, *p_pqk, *p_pattn;
    __half *p_qkvh, *p_xh, *p_wqkvh, *p_wqkh, *p_wprojh, *p_wth, *p_finh;
    cudaGetSymbolAddress((void**)&p_qkvh,  g_qkv_h);
    cudaGetSymbolAddress((void**)&p_out1,  g_out1);
    cudaGetSymbolAddress((void**)&p_pqk,   g_pqk);
    cudaGetSymbolAddress((void**)&p_pattn, g_pattn);
    cudaGetSymbolAddress((void**)&p_xh,    g_x_h);
    cudaGetSymbolAddress((void**)&p_wqkvh, g_wqkv_h);
    cudaGetSymbolAddress((void**)&p_wqkh,  g_wqk_h);
    cudaGetSymbolAddress((void**)&p_wprojh,g_wproj_h);
    cudaGetSymbolAddress((void**)&p_wth,   g_wt_h);
    cudaGetSymbolAddress((void**)&p_finh,  g_fin_h);

    cudaFuncSetAttribute(mma_gemm, cudaFuncAttributeMaxDynamicSharedMemorySize, SMEM_TOT);

    // fp32 -> fp16 converts
    {
        int n4 = (M1 * CC) / 4;
        cvt_kernel<<<(n4 + 255) / 256, 256>>>((const float4*)x, p_xh, n4);
        n4 = (3 * CC * CC) / 4;
        cvt_kernel<<<(n4 + 255) / 256, 256>>>((const float4*)w_qkv, p_wqkvh, n4);
        n4 = (2 * CC * CC) / 4;
        cvt_kernel<<<(n4 + 255) / 256, 256>>>((const float4*)w_qk, p_wqkh, n4);
        n4 = (CC * CC) / 4;
        cvt_kernel<<<(n4 + 255) / 256, 256>>>((const float4*)w_proj, p_wprojh, n4);
    }

    // K1: qkv = x @ w_qkv^T  (102400 x 1152, K=384), fp16 output
    mma_gemm<<<dim3(3 * CC / 128, M1 / 128), 256, SMEM_TOT>>>(
        p_xh, p_wqkvh, nullptr, nullptr, p_qkvh, 3 * CC, CC);

    // K2: window attention + residual
    win_attn_kernel<<<dim3(BB * WN, NH), 256>>>(p_qkvh, x, p_out1);

    // K3a: LN + GELU -> fp16
    ln_gelu_kernel<<<M2, 128>>>(p_out1, ln_g, ln_b, p_wth);

    // K3b: pqk = wintok @ w_qk^T  (2048 x 768, K=384), fp32 output
    mma_gemm<<<dim3(2 * CC / 128, M2 / 128), 256, SMEM_TOT>>>(
        p_wth, p_wqkh, nullptr, p_pqk, nullptr, 2 * CC, CC);

    // K4: pooled attention softmax
    pool_attn_kernel<<<dim3(BB, NH), 256>>>(p_pqk, p_pattn);

    // K5: PSA mix (+ residual via identity) + rearrange -> fp16
    psa_kernel<<<dim3(BB * NH, WS), 224>>>(p_pattn, p_out1, p_finh);

    // K6: out = final @ w_proj^T + b_proj  (100352 x 384, K=384), fp32 output
    mma_gemm<<<dim3(CC / 128, M3 / 128), 256, SMEM_TOT>>>(
        p_finh, p_wprojh, b_proj, out, nullptr, CC, CC);
}

// round 16
// speedup vs baseline: 2.6803x; 1.1178x over previous
#include <cuda_runtime.h>
#include <cuda_fp16.h>
#include <cstdint>
#include <math.h>

// ---------------- problem constants ----------------
#define BB   32
#define WN   64
#define NT   50
#define CC   384
#define NH   12
#define DD   32
#define WS   7
#define HW   3136
#define SCALE 0.17677669529663687f

#define M1 (BB*WN*NT)   // 102400
#define M2 (BB*WN)      // 2048
#define M3 (BB*HW)      // 100352

// ---------------- device scratch ----------------
__device__ __half g_qkv_h[(size_t)M1*3*CC];     // fp16 qkv
__device__ __half g_out1h[(size_t)M1*CC];       // fp16 attn-out + residual
__device__ float g_pqk  [(size_t)M2*2*CC];
__device__ float g_pattn[(size_t)BB*NH*WN*WN];

__device__ __half g_x_h   [(size_t)M1*CC];
__device__ __half g_wqkv_h[3*CC*CC];
__device__ __half g_wqk_h [2*CC*CC];
__device__ __half g_wproj_h[CC*CC];
__device__ __half g_wt_h  [(size_t)M2*CC];
__device__ __half g_fin_h [(size_t)M3*CC];

// ---------------- PTX helpers (baseline ISA only) ----------------
__device__ __forceinline__ uint32_t smem_u32(const void* p) {
    uint32_t r;
    asm("{ .reg .u64 t; cvta.to.shared.u64 t, %1; cvt.u32.u64 %0, t; }" : "=r"(r) : "l"(p));
    return r;
}
__device__ __forceinline__ void cpa16(uint32_t s, const void* g) {
    asm volatile("cp.async.cg.shared.global [%0], [%1], 16;" :: "r"(s), "l"(g));
}
__device__ __forceinline__ void cpa_commit() {
    asm volatile("cp.async.commit_group;" ::: "memory");
}
template<int N>
__device__ __forceinline__ void cpa_wait() {
    asm volatile("cp.async.wait_group %0;" :: "n"(N) : "memory");
}
__device__ __forceinline__ void ldsm_x4(uint32_t& r0, uint32_t& r1, uint32_t& r2, uint32_t& r3,
                                        uint32_t a) {
    asm volatile("ldmatrix.sync.aligned.m8n8.x4.shared.b16 {%0,%1,%2,%3}, [%4];"
                 : "=r"(r0), "=r"(r1), "=r"(r2), "=r"(r3) : "r"(a));
}
__device__ __forceinline__ void ldsm_x2(uint32_t& r0, uint32_t& r1, uint32_t a) {
    asm volatile("ldmatrix.sync.aligned.m8n8.x2.shared.b16 {%0,%1}, [%2];"
                 : "=r"(r0), "=r"(r1) : "r"(a));
}
__device__ __forceinline__ void mma_f16(float* d, const uint32_t* a, const uint32_t* b) {
    asm volatile(
        "mma.sync.aligned.m16n8k16.row.col.f32.f16.f16.f32 "
        "{%0,%1,%2,%3}, {%4,%5,%6,%7}, {%8,%9}, {%0,%1,%2,%3};"
        : "+f"(d[0]), "+f"(d[1]), "+f"(d[2]), "+f"(d[3])
        : "r"(a[0]), "r"(a[1]), "r"(a[2]), "r"(a[3]), "r"(b[0]), "r"(b[1]));
}

// ---------------- fp32 -> fp16 convert ----------------
__global__ void cvt_kernel(const float4* __restrict__ in,
                           __half* __restrict__ out, int n4)
{
    int i = blockIdx.x * 256 + threadIdx.x;
    if (i >= n4) return;
    float4 v = in[i];
    union { __half h[4]; uint2 u; } H;
    H.h[0] = __float2half_rn(v.x);
    H.h[1] = __float2half_rn(v.y);
    H.h[2] = __float2half_rn(v.z);
    H.h[3] = __float2half_rn(v.w);
    *reinterpret_cast<uint2*>(out + (size_t)i * 4) = H.u;
}

// ---------------- fp16 HMMA GEMM (128x128x64, 2 CTA/SM, BK=64) --------------
#define BKH   64
#define PITCH 144
#define PLANE (128 * PITCH)
#define BUF_B (2 * PLANE)
#define SMEM_TOT (2 * BUF_B)

__device__ __forceinline__ void load_plane(uint32_t dst, const __half* __restrict__ G,
                                           int row0, int k0, int K, int tid)
{
    #pragma unroll
    for (int i = 0; i < 4; i++) {
        int seg = tid + i * 256;
        int r = seg >> 3, u = seg & 7;
        cpa16(dst + r * PITCH + u * 16, G + (size_t)(row0 + r) * K + k0 + u * 8);
    }
}

__global__ void __launch_bounds__(256, 2)
mma_gemm(const __half* __restrict__ A, const __half* __restrict__ W,
         const float* __restrict__ bias, float* __restrict__ C,
         __half* __restrict__ Ch, int N, int K)
{
    extern __shared__ __align__(128) char dsm[];
    const int tid  = threadIdx.x;
    const int lane = tid & 31;
    const int wid  = tid >> 5;
    const int wm   = wid & 1;
    const int wn   = wid >> 1;
    const int m0 = blockIdx.y * 128;
    const int n0 = blockIdx.x * 128;
    const uint32_t sb = smem_u32(dsm);

    float acc[4][4][4];
    #pragma unroll
    for (int mi = 0; mi < 4; mi++)
        #pragma unroll
        for (int ni = 0; ni < 4; ni++)
            #pragma unroll
            for (int f = 0; f < 4; f++) acc[mi][ni][f] = 0.f;

    const int NC = K / BKH;

    {
        load_plane(sb + 0 * PLANE, A, m0, 0, K, tid);
        load_plane(sb + 1 * PLANE, W, n0, 0, K, tid);
        cpa_commit();
    }

    const int l16 = lane & 15;
    const uint32_t a_row = wm * 64 + l16;
    const uint32_t a_cb  = ((lane >> 4) & 1) * 16;
    const uint32_t b_row = wn * 32 + (l16 & 7);
    const uint32_t b_cb  = (l16 >> 3) * 16;

    for (int c = 0; c < NC; c++) {
        if (c + 1 < NC) {
            uint32_t buf = sb + ((c + 1) & 1) * BUF_B;
            load_plane(buf + 0 * PLANE, A, m0, (c + 1) * BKH, K, tid);
            load_plane(buf + 1 * PLANE, W, n0, (c + 1) * BKH, K, tid);
            cpa_commit();
            cpa_wait<1>();
        } else {
            cpa_wait<0>();
        }
        __syncthreads();

        const uint32_t buf = sb + (c & 1) * BUF_B;
        #pragma unroll
        for (int ks = 0; ks < 4; ks++) {
            uint32_t a[4][4], b[4][2];
            #pragma unroll
            for (int mi = 0; mi < 4; mi++) {
                uint32_t off = (a_row + mi * 16) * PITCH + ks * 32 + a_cb;
                ldsm_x4(a[mi][0], a[mi][1], a[mi][2], a[mi][3], buf + 0 * PLANE + off);
            }
            #pragma unroll
            for (int ni = 0; ni < 4; ni++) {
                uint32_t off = (b_row + ni * 8) * PITCH + ks * 32 + b_cb;
                ldsm_x2(b[ni][0], b[ni][1], buf + 1 * PLANE + off);
            }
            #pragma unroll
            for (int mi = 0; mi < 4; mi++)
                #pragma unroll
                for (int ni = 0; ni < 4; ni++)
                    mma_f16(acc[mi][ni], a[mi], b[ni]);
        }
        __syncthreads();
    }

    const int rr = lane >> 2, cp = (lane & 3) * 2;
    if (Ch) {
        #pragma unroll
        for (int mi = 0; mi < 4; mi++) {
            int row = m0 + wm * 64 + mi * 16 + rr;
            #pragma unroll
            for (int ni = 0; ni < 4; ni++) {
                int col = n0 + wn * 32 + ni * 8 + cp;
                __half2* p = reinterpret_cast<__half2*>(Ch + (size_t)row * N + col);
                *p = __floats2half2_rn(acc[mi][ni][0], acc[mi][ni][1]);
                __half2* q = reinterpret_cast<__half2*>(Ch + (size_t)(row + 8) * N + col);
                *q = __floats2half2_rn(acc[mi][ni][2], acc[mi][ni][3]);
            }
        }
    } else {
        #pragma unroll
        for (int mi = 0; mi < 4; mi++) {
            int row = m0 + wm * 64 + mi * 16 + rr;
            #pragma unroll
            for (int ni = 0; ni < 4; ni++) {
                int col = n0 + wn * 32 + ni * 8 + cp;
                float b0 = 0.f, b1 = 0.f;
                if (bias) { b0 = bias[col]; b1 = bias[col + 1]; }
                float* p = C + (size_t)row * N + col;
                p[0] = acc[mi][ni][0] + b0;
                p[1] = acc[mi][ni][1] + b1;
                float* q = p + (size_t)8 * N;
                q[0] = acc[mi][ni][2] + b0;
                q[1] = acc[mi][ni][3] + b1;
            }
        }
    }
}

// ---------------- K2: window attention + residual -> fp16 out1 --------------
#define QP 36
#define AP 52
__global__ void __launch_bounds__(256)
win_attn_kernel(const __half* __restrict__ qkv,
                const float* __restrict__ x,
                __half* __restrict__ out1)
{
    const int bw = blockIdx.x;
    const int hh = blockIdx.y;
    __shared__ __align__(16) float q[NT][QP];
    __shared__ __align__(16) float k[NT][QP];
    __shared__ __align__(16) float v[NT][QP];
    __shared__ __align__(16) float at[NT][AP];
    const int tid  = threadIdx.x;
    const int warp = tid >> 5, lane = tid & 31;

    {
        const __half* base = qkv + (size_t)bw * NT * (3 * CC) + hh * DD;
        for (int seg = tid; seg < NT * 12; seg += 256) {
            int i = seg / 12, r = seg % 12;
            int t = r >> 2, u = r & 3;
            const __half* p = base + (size_t)i * (3 * CC) + t * CC + u * 8;
            union { uint4 raw; __half2 h2[4]; } U;
            U.raw = *reinterpret_cast<const uint4*>(p);
            float* dst = (t == 0 ? &q[i][u * 8] : t == 1 ? &k[i][u * 8] : &v[i][u * 8]);
            #pragma unroll
            for (int j = 0; j < 4; j++) {
                float2 f = __half22float2(U.h2[j]);
                dst[j * 2] = f.x; dst[j * 2 + 1] = f.y;
            }
        }
    }
    __syncthreads();

    for (int u = tid; u < 650; u += 256) {
        const int ig = u / 50, j = u % 50;
        const int i0 = ig * 4;
        const int i1 = (i0 + 1 < NT) ? i0 + 1 : NT - 1;
        const int i2 = (i0 + 2 < NT) ? i0 + 2 : NT - 1;
        const int i3 = (i0 + 3 < NT) ? i0 + 3 : NT - 1;
        float a0 = 0.f, a1 = 0.f, a2 = 0.f, a3 = 0.f;
        #pragma unroll
        for (int d4 = 0; d4 < 8; d4++) {
            float4 kv = *reinterpret_cast<const float4*>(&k[j][d4 * 4]);
            float4 q0 = *reinterpret_cast<const float4*>(&q[i0][d4 * 4]);
            float4 q1 = *reinterpret_cast<const float4*>(&q[i1][d4 * 4]);
            float4 q2 = *reinterpret_cast<const float4*>(&q[i2][d4 * 4]);
            float4 q3 = *reinterpret_cast<const float4*>(&q[i3][d4 * 4]);
            a0 += q0.x * kv.x + q0.y * kv.y + q0.z * kv.z + q0.w * kv.w;
            a1 += q1.x * kv.x + q1.y * kv.y + q1.z * kv.z + q1.w * kv.w;
            a2 += q2.x * kv.x + q2.y * kv.y + q2.z * kv.z + q2.w * kv.w;
            a3 += q3.x * kv.x + q3.y * kv.y + q3.z * kv.z + q3.w * kv.w;
        }
        at[i0][j] = a0 * SCALE;
        if (i0 + 1 < NT) at[i0 + 1][j] = a1 * SCALE;
        if (i0 + 2 < NT) at[i0 + 2][j] = a2 * SCALE;
        if (i0 + 3 < NT) at[i0 + 3][j] = a3 * SCALE;
    }
    __syncthreads();

    for (int i = warp; i < NT; i += 8) {
        float a0 = at[i][lane];
        float a1 = (lane < 18) ? at[i][32 + lane] : -1e30f;
        float m = fmaxf(a0, a1);
        #pragma unroll
        for (int o = 16; o; o >>= 1) m = fmaxf(m, __shfl_xor_sync(0xFFFFFFFFu, m, o));
        float e0 = __expf(a0 - m);
        float e1 = (lane < 18) ? __expf(a1 - m) : 0.f;
        float s = e0 + e1;
        #pragma unroll
        for (int o = 16; o; o >>= 1) s += __shfl_xor_sync(0xFFFFFFFFu, s, o);
        float inv = 1.f / s;
        at[i][lane] = e0 * inv;
        if (lane < 18) at[i][32 + lane] = e1 * inv;
    }
    __syncthreads();

    for (int u = tid; u < 416; u += 256) {
        const int ig = u >> 5, dd = u & 31;
        const int i0 = ig * 4;
        const int i1 = (i0 + 1 < NT) ? i0 + 1 : NT - 1;
        const int i2 = (i0 + 2 < NT) ? i0 + 2 : NT - 1;
        const int i3 = (i0 + 3 < NT) ? i0 + 3 : NT - 1;
        float a0 = 0.f, a1 = 0.f, a2 = 0.f, a3 = 0.f;
        #pragma unroll
        for (int j4 = 0; j4 < 12; j4++) {
            float v0 = v[j4 * 4 + 0][dd], v1 = v[j4 * 4 + 1][dd];
            float v2 = v[j4 * 4 + 2][dd], v3 = v[j4 * 4 + 3][dd];
            float4 p0 = *reinterpret_cast<const float4*>(&at[i0][j4 * 4]);
            float4 p1 = *reinterpret_cast<const float4*>(&at[i1][j4 * 4]);
            float4 p2 = *reinterpret_cast<const float4*>(&at[i2][j4 * 4]);
            float4 p3 = *reinterpret_cast<const float4*>(&at[i3][j4 * 4]);
            a0 += p0.x * v0 + p0.y * v1 + p0.z * v2 + p0.w * v3;
            a1 += p1.x * v0 + p1.y * v1 + p1.z * v2 + p1.w * v3;
            a2 += p2.x * v0 + p2.y * v1 + p2.z * v2 + p2.w * v3;
            a3 += p3.x * v0 + p3.y * v1 + p3.z * v2 + p3.w * v3;
        }
        {
            float v0 = v[48][dd], v1 = v[49][dd];
            a0 += at[i0][48] * v0 + at[i0][49] * v1;
            a1 += at[i1][48] * v0 + at[i1][49] * v1;
            a2 += at[i2][48] * v0 + at[i2][49] * v1;
            a3 += at[i3][48] * v0 + at[i3][49] * v1;
        }
        const size_t ob = (size_t)bw * NT * CC + hh * DD + dd;
        float r[4] = {a0, a1, a2, a3};
        #pragma unroll
        for (int t = 0; t < 4; t++) {
            int i = i0 + t;
            if (i < NT) {
                size_t o = ob + (size_t)i * CC;
                out1[o] = __float2half_rn(r[t] + x[o]);
            }
        }
    }
}

// ---------------- K3a: LayerNorm + exact GELU (fp16 in) -> fp16 -------------
__global__ void ln_gelu_kernel(const __half* __restrict__ out1,
                               const float* __restrict__ g,
                               const float* __restrict__ b,
                               __half* __restrict__ wt_h)
{
    const int bw = blockIdx.x;
    const int tid = threadIdx.x; // 128
    const __half* row = out1 + (size_t)bw * NT * CC;
    float vv[3], s = 0.f, s2 = 0.f;
    #pragma unroll
    for (int i = 0; i < 3; i++) {
        vv[i] = __half2float(row[tid + i * 128]);
        s += vv[i]; s2 += vv[i] * vv[i];
    }
    __shared__ float rs[4], rs2[4];
    #pragma unroll
    for (int o = 16; o; o >>= 1) {
        s  += __shfl_down_sync(0xFFFFFFFFu, s,  o);
        s2 += __shfl_down_sync(0xFFFFFFFFu, s2, o);
    }
    if ((tid & 31) == 0) { rs[tid >> 5] = s; rs2[tid >> 5] = s2; }
    __syncthreads();
    float S  = rs[0] + rs[1] + rs[2] + rs[3];
    float S2 = rs2[0] + rs2[1] + rs2[2] + rs2[3];
    float mean = S / (float)CC;
    float var  = S2 / (float)CC - mean * mean;
    float inv  = rsqrtf(var + 1e-5f);
    #pragma unroll
    for (int i = 0; i < 3; i++) {
        int c = tid + i * 128;
        float nz = (vv[i] - mean) * inv * g[c] + b[c];
        float ge = 0.5f * nz * (1.f + erff(nz * 0.70710678118654752f));
        wt_h[(size_t)bw * CC + c] = __float2half_rn(ge);
    }
}

// ---------------- K4: pooled attention softmax (warp-parallel) --------------
__global__ void pool_attn_kernel(const float* __restrict__ pqk,
                                 float* __restrict__ pattn)
{
    const int b = blockIdx.x, hh = blockIdx.y;
    __shared__ float pq[WN][32];
    __shared__ float pk[WN][33];
    __shared__ float sc[WN][WN];
    const int tid = threadIdx.x; // 256
    const int warp = tid >> 5, lane = tid & 31;

    for (int idx = tid; idx < WN * 32; idx += 256) {
        int w = idx >> 5, d = idx & 31;
        size_t base = (size_t)(b * WN + w) * (2 * CC) + hh * DD + d;
        pq[w][d] = pqk[base];
        pk[w][d] = pqk[base + CC];
    }
    __syncthreads();

    for (int idx = tid; idx < WN * WN; idx += 256) {
        int w = idx >> 6, vv = idx & 63;
        float s = 0.f;
        #pragma unroll
        for (int d = 0; d < 32; d++) s += pq[w][d] * pk[vv][d];
        sc[w][vv] = s * SCALE;
    }
    __syncthreads();

    for (int i = warp; i < WN; i += 8) {
        float a0 = sc[i][lane];
        float a1 = sc[i][32 + lane];
        float m = fmaxf(a0, a1);
        #pragma unroll
        for (int o = 16; o; o >>= 1) m = fmaxf(m, __shfl_xor_sync(0xFFFFFFFFu, m, o));
        float e0 = __expf(a0 - m);
        float e1 = __expf(a1 - m);
        float s = e0 + e1;
        #pragma unroll
        for (int o = 16; o; o >>= 1) s += __shfl_xor_sync(0xFFFFFFFFu, s, o);
        float inv = 1.f / s;
        sc[i][lane] = e0 * inv;
        sc[i][32 + lane] = e1 * inv;
    }
    __syncthreads();

    float* dst = pattn + (size_t)(b * NH + hh) * WN * WN;
    for (int idx = tid; idx < WN * WN; idx += 256) dst[idx] = sc[idx >> 6][idx & 63];
}

// ---------------- K5 v4: PSA mix, float4 sp + (sp + I) trick -> fp16 --------
__global__ void __launch_bounds__(224)
psa_kernel(const float* __restrict__ pattn,
           const __half* __restrict__ out1,
           __half* __restrict__ fin_h)
{
    const int bh = blockIdx.x;
    const int b = bh / NH, hh = bh % NH;
    const int si = blockIdx.y;
    __shared__ __align__(16) float sp[WN][WN];
    const int tid = threadIdx.x; // 224

    const float* src = pattn + (size_t)bh * WN * WN;
    for (int idx = tid; idx < WN * WN; idx += 224) sp[idx >> 6][idx & 63] = src[idx];
    __syncthreads();
    if (tid < WN) sp[tid][tid] += 1.0f;   // fold residual into the matrix
    __syncthreads();

    const int sj = tid >> 5, dd = tid & 31;
    const int s = si * 7 + sj;
    const int col = hh * DD + dd;

    float acc[WN];
    #pragma unroll
    for (int w = 0; w < WN; w++) acc[w] = 0.f;

    const __half* pbase = out1 + ((size_t)b * WN * NT + s + 1) * CC + col;
    const size_t wstride = (size_t)NT * CC;

    for (int v4 = 0; v4 < 16; v4++) {
        float b0 = __half2float(pbase[(size_t)(v4 * 4 + 0) * wstride]);
        float b1 = __half2float(pbase[(size_t)(v4 * 4 + 1) * wstride]);
        float b2 = __half2float(pbase[(size_t)(v4 * 4 + 2) * wstride]);
        float b3 = __half2float(pbase[(size_t)(v4 * 4 + 3) * wstride]);
        #pragma unroll
        for (int w = 0; w < WN; w++) {
            float4 spv = *reinterpret_cast<const float4*>(&sp[w][v4 * 4]);
            acc[w] += spv.x * b0 + spv.y * b1 + spv.z * b2 + spv.w * b3;
        }
    }

    for (int w = 0; w < WN; w++) {
        int hi = w >> 3, wi = w & 7;
        int y = hi * WS + si, xx = wi * WS + sj;
        size_t o = ((size_t)b * HW + y * 56 + xx) * CC + col;
        fin_h[o] = __float2half_rn(acc[w]);
    }
}

// ---------------- launch ----------------
extern "C" void kernel_launch(void* const* d_in, const int* in_sizes, int n_in,
                              void* d_out, int out_size)
{
    const float* x      = (const float*)d_in[0];
    const float* w_qkv  = (const float*)d_in[3];
    const float* w_qk   = (const float*)d_in[4];
    const float* ln_g   = (const float*)d_in[5];
    const float* ln_b   = (const float*)d_in[6];
    const float* w_proj = (const float*)d_in[7];
    const float* b_proj = (const float*)d_in[8];
    float* out = (float*)d_out;

    float *p_pqk, *p_pattn;
    __half *p_qkvh, *p_out1h, *p_xh, *p_wqkvh, *p_wqkh, *p_wprojh, *p_wth, *p_finh;
    cudaGetSymbolAddress((void**)&p_qkvh,  g_qkv_h);
    cudaGetSymbolAddress((void**)&p_out1h, g_out1h);
    cudaGetSymbolAddress((void**)&p_pqk,   g_pqk);
    cudaGetSymbolAddress((void**)&p_pattn, g_pattn);
    cudaGetSymbolAddress((void**)&p_xh,    g_x_h);
    cudaGetSymbolAddress((void**)&p_wqkvh, g_wqkv_h);
    cudaGetSymbolAddress((void**)&p_wqkh,  g_wqk_h);
    cudaGetSymbolAddress((void**)&p_wprojh,g_wproj_h);
    cudaGetSymbolAddress((void**)&p_wth,   g_wt_h);
    cudaGetSymbolAddress((void**)&p_finh,  g_fin_h);

    cudaFuncSetAttribute(mma_gemm, cudaFuncAttributeMaxDynamicSharedMemorySize, SMEM_TOT);

    // fp32 -> fp16 converts
    {
        int n4 = (M1 * CC) / 4;
        cvt_kernel<<<(n4 + 255) / 256, 256>>>((const float4*)x, p_xh, n4);
        n4 = (3 * CC * CC) / 4;
        cvt_kernel<<<(n4 + 255) / 256, 256>>>((const float4*)w_qkv, p_wqkvh, n4);
        n4 = (2 * CC * CC) / 4;
        cvt_kernel<<<(n4 + 255) / 256, 256>>>((const float4*)w_qk, p_wqkh, n4);
        n4 = (CC * CC) / 4;
        cvt_kernel<<<(n4 + 255) / 256, 256>>>((const float4*)w_proj, p_wprojh, n4);
    }

    // K1: qkv = x @ w_qkv^T  (102400 x 1152, K=384), fp16 output
    mma_gemm<<<dim3(3 * CC / 128, M1 / 128), 256, SMEM_TOT>>>(
        p_xh, p_wqkvh, nullptr, nullptr, p_qkvh, 3 * CC, CC);

    // K2: window attention + residual -> fp16 out1
    win_attn_kernel<<<dim3(BB * WN, NH), 256>>>(p_qkvh, x, p_out1h);

    // K3a: LN + GELU -> fp16
    ln_gelu_kernel<<<M2, 128>>>(p_out1h, ln_g, ln_b, p_wth);

    // K3b: pqk = wintok @ w_qk^T  (2048 x 768, K=384), fp32 output
    mma_gemm<<<dim3(2 * CC / 128, M2 / 128), 256, SMEM_TOT>>>(
        p_wth, p_wqkh, nullptr, p_pqk, nullptr, 2 * CC, CC);

    // K4: pooled attention softmax
    pool_attn_kernel<<<dim3(BB, NH), 256>>>(p_pqk, p_pattn);

    // K5: PSA mix (+ residual via identity) + rearrange -> fp16
    psa_kernel<<<dim3(BB * NH, WS), 224>>>(p_pattn, p_out1h, p_finh);

    // K6: out = final @ w_proj^T + b_proj  (100352 x 384, K=384), fp32 output
    mma_gemm<<<dim3(CC / 128, M3 / 128), 256, SMEM_TOT>>>(
        p_finh, p_wprojh, b_proj, out, nullptr, CC, CC);
}

// round 17
// speedup vs baseline: 2.7114x; 1.0116x over previous
#include <cuda_runtime.h>
#include <cuda_fp16.h>
#include <cstdint>
#include <math.h>

// ---------------- problem constants ----------------
#define BB   32
#define WN   64
#define NT   50
#define CC   384
#define NH   12
#define DD   32
#define WS   7
#define HW   3136
#define SCALE 0.17677669529663687f

#define M1 (BB*WN*NT)   // 102400
#define M2 (BB*WN)      // 2048
#define M3 (BB*HW)      // 100352

// ---------------- device scratch ----------------
__device__ __half g_qkv_h[(size_t)M1*3*CC];     // fp16 qkv
__device__ __half g_out1h[(size_t)M1*CC];       // fp16 attn-out + residual
__device__ float g_pqk  [(size_t)M2*2*CC];
__device__ float g_pattn[(size_t)BB*NH*WN*WN];

__device__ __half g_x_h   [(size_t)M1*CC];
__device__ __half g_wqkv_h[3*CC*CC];
__device__ __half g_wqk_h [2*CC*CC];
__device__ __half g_wproj_h[CC*CC];
__device__ __half g_wt_h  [(size_t)M2*CC];
__device__ __half g_fin_h [(size_t)M3*CC];

// ---------------- PTX helpers (baseline ISA only) ----------------
__device__ __forceinline__ uint32_t smem_u32(const void* p) {
    uint32_t r;
    asm("{ .reg .u64 t; cvta.to.shared.u64 t, %1; cvt.u32.u64 %0, t; }" : "=r"(r) : "l"(p));
    return r;
}
__device__ __forceinline__ void cpa16(uint32_t s, const void* g) {
    asm volatile("cp.async.cg.shared.global [%0], [%1], 16;" :: "r"(s), "l"(g));
}
__device__ __forceinline__ void cpa_commit() {
    asm volatile("cp.async.commit_group;" ::: "memory");
}
template<int N>
__device__ __forceinline__ void cpa_wait() {
    asm volatile("cp.async.wait_group %0;" :: "n"(N) : "memory");
}
__device__ __forceinline__ void ldsm_x4(uint32_t& r0, uint32_t& r1, uint32_t& r2, uint32_t& r3,
                                        uint32_t a) {
    asm volatile("ldmatrix.sync.aligned.m8n8.x4.shared.b16 {%0,%1,%2,%3}, [%4];"
                 : "=r"(r0), "=r"(r1), "=r"(r2), "=r"(r3) : "r"(a));
}
__device__ __forceinline__ void ldsm_x2(uint32_t& r0, uint32_t& r1, uint32_t a) {
    asm volatile("ldmatrix.sync.aligned.m8n8.x2.shared.b16 {%0,%1}, [%2];"
                 : "=r"(r0), "=r"(r1) : "r"(a));
}
__device__ __forceinline__ void mma_f16(float* d, const uint32_t* a, const uint32_t* b) {
    asm volatile(
        "mma.sync.aligned.m16n8k16.row.col.f32.f16.f16.f32 "
        "{%0,%1,%2,%3}, {%4,%5,%6,%7}, {%8,%9}, {%0,%1,%2,%3};"
        : "+f"(d[0]), "+f"(d[1]), "+f"(d[2]), "+f"(d[3])
        : "r"(a[0]), "r"(a[1]), "r"(a[2]), "r"(a[3]), "r"(b[0]), "r"(b[1]));
}

// ---------------- fp32 -> fp16 convert ----------------
__global__ void cvt_kernel(const float4* __restrict__ in,
                           __half* __restrict__ out, int n4)
{
    int i = blockIdx.x * 256 + threadIdx.x;
    if (i >= n4) return;
    float4 v = in[i];
    union { __half h[4]; uint2 u; } H;
    H.h[0] = __float2half_rn(v.x);
    H.h[1] = __float2half_rn(v.y);
    H.h[2] = __float2half_rn(v.z);
    H.h[3] = __float2half_rn(v.w);
    *reinterpret_cast<uint2*>(out + (size_t)i * 4) = H.u;
}

// ---------------- fp16 HMMA GEMM (128x128x64, 2 CTA/SM, 3-stage) ------------
#define BKH   64
#define PITCH 144
#define PLANE (128 * PITCH)
#define BUF_B (2 * PLANE)          // 36864 B per stage
#define SMEM_TOT (3 * BUF_B)       // 110592 B

__device__ __forceinline__ void load_plane(uint32_t dst, const __half* __restrict__ G,
                                           int row0, int k0, int K, int tid)
{
    #pragma unroll
    for (int i = 0; i < 4; i++) {
        int seg = tid + i * 256;
        int r = seg >> 3, u = seg & 7;
        cpa16(dst + r * PITCH + u * 16, G + (size_t)(row0 + r) * K + k0 + u * 8);
    }
}

__global__ void __launch_bounds__(256, 2)
mma_gemm(const __half* __restrict__ A, const __half* __restrict__ W,
         const float* __restrict__ bias, float* __restrict__ C,
         __half* __restrict__ Ch, int N, int K)
{
    extern __shared__ __align__(128) char dsm[];
    const int tid  = threadIdx.x;
    const int lane = tid & 31;
    const int wid  = tid >> 5;
    const int wm   = wid & 1;
    const int wn   = wid >> 1;
    const int m0 = blockIdx.y * 128;
    const int n0 = blockIdx.x * 128;
    const uint32_t sb = smem_u32(dsm);

    float acc[4][4][4];
    #pragma unroll
    for (int mi = 0; mi < 4; mi++)
        #pragma unroll
        for (int ni = 0; ni < 4; ni++)
            #pragma unroll
            for (int f = 0; f < 4; f++) acc[mi][ni][f] = 0.f;

    const int NC = K / BKH;            // 6

    // prologue: prefetch chunks 0 and 1 into stages 0 and 1
    {
        load_plane(sb + 0 * BUF_B + 0 * PLANE, A, m0, 0, K, tid);
        load_plane(sb + 0 * BUF_B + 1 * PLANE, W, n0, 0, K, tid);
        cpa_commit();
        load_plane(sb + 1 * BUF_B + 0 * PLANE, A, m0, BKH, K, tid);
        load_plane(sb + 1 * BUF_B + 1 * PLANE, W, n0, BKH, K, tid);
        cpa_commit();
    }

    const int l16 = lane & 15;
    const uint32_t a_row = wm * 64 + l16;
    const uint32_t a_cb  = ((lane >> 4) & 1) * 16;
    const uint32_t b_row = wn * 32 + (l16 & 7);
    const uint32_t b_cb  = (l16 >> 3) * 16;

    int stage = 0;
    for (int c = 0; c < NC; c++) {
        if (c + 1 < NC) cpa_wait<1>(); else cpa_wait<0>();
        __syncthreads();   // (a) chunk c data visible; (b) all warps done with chunk c-1

        // prefetch chunk c+2 into the stage chunk c-1 just vacated
        if (c + 2 < NC) {
            uint32_t buf = sb + ((stage + 2) % 3) * BUF_B;
            load_plane(buf + 0 * PLANE, A, m0, (c + 2) * BKH, K, tid);
            load_plane(buf + 1 * PLANE, W, n0, (c + 2) * BKH, K, tid);
            cpa_commit();
        }

        const uint32_t buf = sb + stage * BUF_B;
        #pragma unroll
        for (int ks = 0; ks < 4; ks++) {
            uint32_t a[4][4], b[4][2];
            #pragma unroll
            for (int mi = 0; mi < 4; mi++) {
                uint32_t off = (a_row + mi * 16) * PITCH + ks * 32 + a_cb;
                ldsm_x4(a[mi][0], a[mi][1], a[mi][2], a[mi][3], buf + 0 * PLANE + off);
            }
            #pragma unroll
            for (int ni = 0; ni < 4; ni++) {
                uint32_t off = (b_row + ni * 8) * PITCH + ks * 32 + b_cb;
                ldsm_x2(b[ni][0], b[ni][1], buf + 1 * PLANE + off);
            }
            #pragma unroll
            for (int mi = 0; mi < 4; mi++)
                #pragma unroll
                for (int ni = 0; ni < 4; ni++)
                    mma_f16(acc[mi][ni], a[mi], b[ni]);
        }
        stage = (stage + 1) % 3;
    }

    const int rr = lane >> 2, cp = (lane & 3) * 2;
    if (Ch) {
        #pragma unroll
        for (int mi = 0; mi < 4; mi++) {
            int row = m0 + wm * 64 + mi * 16 + rr;
            #pragma unroll
            for (int ni = 0; ni < 4; ni++) {
                int col = n0 + wn * 32 + ni * 8 + cp;
                __half2* p = reinterpret_cast<__half2*>(Ch + (size_t)row * N + col);
                *p = __floats2half2_rn(acc[mi][ni][0], acc[mi][ni][1]);
                __half2* q = reinterpret_cast<__half2*>(Ch + (size_t)(row + 8) * N + col);
                *q = __floats2half2_rn(acc[mi][ni][2], acc[mi][ni][3]);
            }
        }
    } else {
        #pragma unroll
        for (int mi = 0; mi < 4; mi++) {
            int row = m0 + wm * 64 + mi * 16 + rr;
            #pragma unroll
            for (int ni = 0; ni < 4; ni++) {
                int col = n0 + wn * 32 + ni * 8 + cp;
                float b0 = 0.f, b1 = 0.f;
                if (bias) { b0 = bias[col]; b1 = bias[col + 1]; }
                float* p = C + (size_t)row * N + col;
                p[0] = acc[mi][ni][0] + b0;
                p[1] = acc[mi][ni][1] + b1;
                float* q = p + (size_t)8 * N;
                q[0] = acc[mi][ni][2] + b0;
                q[1] = acc[mi][ni][3] + b1;
            }
        }
    }
}

// ---------------- K2: window attention + residual(fp16 x) -> fp16 out1 ------
#define QP 36
#define AP 52
__global__ void __launch_bounds__(256)
win_attn_kernel(const __half* __restrict__ qkv,
                const __half* __restrict__ xh,
                __half* __restrict__ out1)
{
    const int bw = blockIdx.x;
    const int hh = blockIdx.y;
    __shared__ __align__(16) float q[NT][QP];
    __shared__ __align__(16) float k[NT][QP];
    __shared__ __align__(16) float v[NT][QP];
    __shared__ __align__(16) float at[NT][AP];
    const int tid  = threadIdx.x;
    const int warp = tid >> 5, lane = tid & 31;

    {
        const __half* base = qkv + (size_t)bw * NT * (3 * CC) + hh * DD;
        for (int seg = tid; seg < NT * 12; seg += 256) {
            int i = seg / 12, r = seg % 12;
            int t = r >> 2, u = r & 3;
            const __half* p = base + (size_t)i * (3 * CC) + t * CC + u * 8;
            union { uint4 raw; __half2 h2[4]; } U;
            U.raw = *reinterpret_cast<const uint4*>(p);
            float* dst = (t == 0 ? &q[i][u * 8] : t == 1 ? &k[i][u * 8] : &v[i][u * 8]);
            #pragma unroll
            for (int j = 0; j < 4; j++) {
                float2 f = __half22float2(U.h2[j]);
                dst[j * 2] = f.x; dst[j * 2 + 1] = f.y;
            }
        }
    }
    __syncthreads();

    for (int u = tid; u < 650; u += 256) {
        const int ig = u / 50, j = u % 50;
        const int i0 = ig * 4;
        const int i1 = (i0 + 1 < NT) ? i0 + 1 : NT - 1;
        const int i2 = (i0 + 2 < NT) ? i0 + 2 : NT - 1;
        const int i3 = (i0 + 3 < NT) ? i0 + 3 : NT - 1;
        float a0 = 0.f, a1 = 0.f, a2 = 0.f, a3 = 0.f;
        #pragma unroll
        for (int d4 = 0; d4 < 8; d4++) {
            float4 kv = *reinterpret_cast<const float4*>(&k[j][d4 * 4]);
            float4 q0 = *reinterpret_cast<const float4*>(&q[i0][d4 * 4]);
            float4 q1 = *reinterpret_cast<const float4*>(&q[i1][d4 * 4]);
            float4 q2 = *reinterpret_cast<const float4*>(&q[i2][d4 * 4]);
            float4 q3 = *reinterpret_cast<const float4*>(&q[i3][d4 * 4]);
            a0 += q0.x * kv.x + q0.y * kv.y + q0.z * kv.z + q0.w * kv.w;
            a1 += q1.x * kv.x + q1.y * kv.y + q1.z * kv.z + q1.w * kv.w;
            a2 += q2.x * kv.x + q2.y * kv.y + q2.z * kv.z + q2.w * kv.w;
            a3 += q3.x * kv.x + q3.y * kv.y + q3.z * kv.z + q3.w * kv.w;
        }
        at[i0][j] = a0 * SCALE;
        if (i0 + 1 < NT) at[i0 + 1][j] = a1 * SCALE;
        if (i0 + 2 < NT) at[i0 + 2][j] = a2 * SCALE;
        if (i0 + 3 < NT) at[i0 + 3][j] = a3 * SCALE;
    }
    __syncthreads();

    for (int i = warp; i < NT; i += 8) {
        float a0 = at[i][lane];
        float a1 = (lane < 18) ? at[i][32 + lane] : -1e30f;
        float m = fmaxf(a0, a1);
        #pragma unroll
        for (int o = 16; o; o >>= 1) m = fmaxf(m, __shfl_xor_sync(0xFFFFFFFFu, m, o));
        float e0 = __expf(a0 - m);
        float e1 = (lane < 18) ? __expf(a1 - m) : 0.f;
        float s = e0 + e1;
        #pragma unroll
        for (int o = 16; o; o >>= 1) s += __shfl_xor_sync(0xFFFFFFFFu, s, o);
        float inv = 1.f / s;
        at[i][lane] = e0 * inv;
        if (lane < 18) at[i][32 + lane] = e1 * inv;
    }
    __syncthreads();

    for (int u = tid; u < 416; u += 256) {
        const int ig = u >> 5, dd = u & 31;
        const int i0 = ig * 4;
        const int i1 = (i0 + 1 < NT) ? i0 + 1 : NT - 1;
        const int i2 = (i0 + 2 < NT) ? i0 + 2 : NT - 1;
        const int i3 = (i0 + 3 < NT) ? i0 + 3 : NT - 1;
        float a0 = 0.f, a1 = 0.f, a2 = 0.f, a3 = 0.f;
        #pragma unroll
        for (int j4 = 0; j4 < 12; j4++) {
            float v0 = v[j4 * 4 + 0][dd], v1 = v[j4 * 4 + 1][dd];
            float v2 = v[j4 * 4 + 2][dd], v3 = v[j4 * 4 + 3][dd];
            float4 p0 = *reinterpret_cast<const float4*>(&at[i0][j4 * 4]);
            float4 p1 = *reinterpret_cast<const float4*>(&at[i1][j4 * 4]);
            float4 p2 = *reinterpret_cast<const float4*>(&at[i2][j4 * 4]);
            float4 p3 = *reinterpret_cast<const float4*>(&at[i3][j4 * 4]);
            a0 += p0.x * v0 + p0.y * v1 + p0.z * v2 + p0.w * v3;
            a1 += p1.x * v0 + p1.y * v1 + p1.z * v2 + p1.w * v3;
            a2 += p2.x * v0 + p2.y * v1 + p2.z * v2 + p2.w * v3;
            a3 += p3.x * v0 + p3.y * v1 + p3.z * v2 + p3.w * v3;
        }
        {
            float v0 = v[48][dd], v1 = v[49][dd];
            a0 += at[i0][48] * v0 + at[i0][49] * v1;
            a1 += at[i1][48] * v0 + at[i1][49] * v1;
            a2 += at[i2][48] * v0 + at[i2][49] * v1;
            a3 += at[i3][48] * v0 + at[i3][49] * v1;
        }
        const size_t ob = (size_t)bw * NT * CC + hh * DD + dd;
        float r[4] = {a0, a1, a2, a3};
        #pragma unroll
        for (int t = 0; t < 4; t++) {
            int i = i0 + t;
            if (i < NT) {
                size_t o = ob + (size_t)i * CC;
                out1[o] = __float2half_rn(r[t] + __half2float(xh[o]));
            }
        }
    }
}

// ---------------- K3a: LayerNorm + exact GELU (fp16 in) -> fp16 -------------
__global__ void ln_gelu_kernel(const __half* __restrict__ out1,
                               const float* __restrict__ g,
                               const float* __restrict__ b,
                               __half* __restrict__ wt_h)
{
    const int bw = blockIdx.x;
    const int tid = threadIdx.x; // 128
    const __half* row = out1 + (size_t)bw * NT * CC;
    float vv[3], s = 0.f, s2 = 0.f;
    #pragma unroll
    for (int i = 0; i < 3; i++) {
        vv[i] = __half2float(row[tid + i * 128]);
        s += vv[i]; s2 += vv[i] * vv[i];
    }
    __shared__ float rs[4], rs2[4];
    #pragma unroll
    for (int o = 16; o; o >>= 1) {
        s  += __shfl_down_sync(0xFFFFFFFFu, s,  o);
        s2 += __shfl_down_sync(0xFFFFFFFFu, s2, o);
    }
    if ((tid & 31) == 0) { rs[tid >> 5] = s; rs2[tid >> 5] = s2; }
    __syncthreads();
    float S  = rs[0] + rs[1] + rs[2] + rs[3];
    float S2 = rs2[0] + rs2[1] + rs2[2] + rs2[3];
    float mean = S / (float)CC;
    float var  = S2 / (float)CC - mean * mean;
    float inv  = rsqrtf(var + 1e-5f);
    #pragma unroll
    for (int i = 0; i < 3; i++) {
        int c = tid + i * 128;
        float nz = (vv[i] - mean) * inv * g[c] + b[c];
        float ge = 0.5f * nz * (1.f + erff(nz * 0.70710678118654752f));
        wt_h[(size_t)bw * CC + c] = __float2half_rn(ge);
    }
}

// ---------------- K4: pooled attention softmax (warp-parallel) --------------
__global__ void pool_attn_kernel(const float* __restrict__ pqk,
                                 float* __restrict__ pattn)
{
    const int b = blockIdx.x, hh = blockIdx.y;
    __shared__ float pq[WN][32];
    __shared__ float pk[WN][33];
    __shared__ float sc[WN][WN];
    const int tid = threadIdx.x; // 256
    const int warp = tid >> 5, lane = tid & 31;

    for (int idx = tid; idx < WN * 32; idx += 256) {
        int w = idx >> 5, d = idx & 31;
        size_t base = (size_t)(b * WN + w) * (2 * CC) + hh * DD + d;
        pq[w][d] = pqk[base];
        pk[w][d] = pqk[base + CC];
    }
    __syncthreads();

    for (int idx = tid; idx < WN * WN; idx += 256) {
        int w = idx >> 6, vv = idx & 63;
        float s = 0.f;
        #pragma unroll
        for (int d = 0; d < 32; d++) s += pq[w][d] * pk[vv][d];
        sc[w][vv] = s * SCALE;
    }
    __syncthreads();

    for (int i = warp; i < WN; i += 8) {
        float a0 = sc[i][lane];
        float a1 = sc[i][32 + lane];
        float m = fmaxf(a0, a1);
        #pragma unroll
        for (int o = 16; o; o >>= 1) m = fmaxf(m, __shfl_xor_sync(0xFFFFFFFFu, m, o));
        float e0 = __expf(a0 - m);
        float e1 = __expf(a1 - m);
        float s = e0 + e1;
        #pragma unroll
        for (int o = 16; o; o >>= 1) s += __shfl_xor_sync(0xFFFFFFFFu, s, o);
        float inv = 1.f / s;
        sc[i][lane] = e0 * inv;
        sc[i][32 + lane] = e1 * inv;
    }
    __syncthreads();

    float* dst = pattn + (size_t)(b * NH + hh) * WN * WN;
    for (int idx = tid; idx < WN * WN; idx += 256) dst[idx] = sc[idx >> 6][idx & 63];
}

// ---------------- K5: PSA mix, float4 sp + (sp + I) trick -> fp16 -----------
__global__ void __launch_bounds__(224)
psa_kernel(const float* __restrict__ pattn,
           const __half* __restrict__ out1,
           __half* __restrict__ fin_h)
{
    const int bh = blockIdx.x;
    const int b = bh / NH, hh = bh % NH;
    const int si = blockIdx.y;
    __shared__ __align__(16) float sp[WN][WN];
    const int tid = threadIdx.x; // 224

    const float* src = pattn + (size_t)bh * WN * WN;
    for (int idx = tid; idx < WN * WN; idx += 224) sp[idx >> 6][idx & 63] = src[idx];
    __syncthreads();
    if (tid < WN) sp[tid][tid] += 1.0f;
    __syncthreads();

    const int sj = tid >> 5, dd = tid & 31;
    const int s = si * 7 + sj;
    const int col = hh * DD + dd;

    float acc[WN];
    #pragma unroll
    for (int w = 0; w < WN; w++) acc[w] = 0.f;

    const __half* pbase = out1 + ((size_t)b * WN * NT + s + 1) * CC + col;
    const size_t wstride = (size_t)NT * CC;

    for (int v4 = 0; v4 < 16; v4++) {
        float b0 = __half2float(pbase[(size_t)(v4 * 4 + 0) * wstride]);
        float b1 = __half2float(pbase[(size_t)(v4 * 4 + 1) * wstride]);
        float b2 = __half2float(pbase[(size_t)(v4 * 4 + 2) * wstride]);
        float b3 = __half2float(pbase[(size_t)(v4 * 4 + 3) * wstride]);
        #pragma unroll
        for (int w = 0; w < WN; w++) {
            float4 spv = *reinterpret_cast<const float4*>(&sp[w][v4 * 4]);
            acc[w] += spv.x * b0 + spv.y * b1 + spv.z * b2 + spv.w * b3;
        }
    }

    for (int w = 0; w < WN; w++) {
        int hi = w >> 3, wi = w & 7;
        int y = hi * WS + si, xx = wi * WS + sj;
        size_t o = ((size_t)b * HW + y * 56 + xx) * CC + col;
        fin_h[o] = __float2half_rn(acc[w]);
    }
}

// ---------------- launch ----------------
extern "C" void kernel_launch(void* const* d_in, const int* in_sizes, int n_in,
                              void* d_out, int out_size)
{
    const float* x      = (const float*)d_in[0];
    const float* w_qkv  = (const float*)d_in[3];
    const float* w_qk   = (const float*)d_in[4];
    const float* ln_g   = (const float*)d_in[5];
    const float* ln_b   = (const float*)d_in[6];
    const float* w_proj = (const float*)d_in[7];
    const float* b_proj = (const float*)d_in[8];
    float* out = (float*)d_out;

    float *p_pqk, *p_pattn;
    __half *p_qkvh, *p_out1h, *p_xh, *p_wqkvh, *p_wqkh, *p_wprojh, *p_wth, *p_finh;
    cudaGetSymbolAddress((void**)&p_qkvh,  g_qkv_h);
    cudaGetSymbolAddress((void**)&p_out1h, g_out1h);
    cudaGetSymbolAddress((void**)&p_pqk,   g_pqk);
    cudaGetSymbolAddress((void**)&p_pattn, g_pattn);
    cudaGetSymbolAddress((void**)&p_xh,    g_x_h);
    cudaGetSymbolAddress((void**)&p_wqkvh, g_wqkv_h);
    cudaGetSymbolAddress((void**)&p_wqkh,  g_wqk_h);
    cudaGetSymbolAddress((void**)&p_wprojh,g_wproj_h);
    cudaGetSymbolAddress((void**)&p_wth,   g_wt_h);
    cudaGetSymbolAddress((void**)&p_finh,  g_fin_h);

    cudaFuncSetAttribute(mma_gemm, cudaFuncAttributeMaxDynamicSharedMemorySize, SMEM_TOT);

    // fp32 -> fp16 converts
    {
        int n4 = (M1 * CC) / 4;
        cvt_kernel<<<(n4 + 255) / 256, 256>>>((const float4*)x, p_xh, n4);
        n4 = (3 * CC * CC) / 4;
        cvt_kernel<<<(n4 + 255) / 256, 256>>>((const float4*)w_qkv, p_wqkvh, n4);
        n4 = (2 * CC * CC) / 4;
        cvt_kernel<<<(n4 + 255) / 256, 256>>>((const float4*)w_qk, p_wqkh, n4);
        n4 = (CC * CC) / 4;
        cvt_kernel<<<(n4 + 255) / 256, 256>>>((const float4*)w_proj, p_wprojh, n4);
    }

    // K1: qkv = x @ w_qkv^T  (102400 x 1152, K=384), fp16 output
    mma_gemm<<<dim3(3 * CC / 128, M1 / 128), 256, SMEM_TOT>>>(
        p_xh, p_wqkvh, nullptr, nullptr, p_qkvh, 3 * CC, CC);

    // K2: window attention + residual -> fp16 out1
    win_attn_kernel<<<dim3(BB * WN, NH), 256>>>(p_qkvh, p_xh, p_out1h);

    // K3a: LN + GELU -> fp16
    ln_gelu_kernel<<<M2, 128>>>(p_out1h, ln_g, ln_b, p_wth);

    // K3b: pqk = wintok @ w_qk^T  (2048 x 768, K=384), fp32 output
    mma_gemm<<<dim3(2 * CC / 128, M2 / 128), 256, SMEM_TOT>>>(
        p_wth, p_wqkh, nullptr, p_pqk, nullptr, 2 * CC, CC);

    // K4: pooled attention softmax
    pool_attn_kernel<<<dim3(BB, NH), 256>>>(p_pqk, p_pattn);

    // K5: PSA mix (+ residual via identity) + rearrange -> fp16
    psa_kernel<<<dim3(BB * NH, WS), 224>>>(p_pattn, p_out1h, p_finh);

    // K6: out = final @ w_proj^T + b_proj  (100352 x 384, K=384), fp32 output
    mma_gemm<<<dim3(CC / 128, M3 / 128), 256, SMEM_TOT>>>(
        p_finh, p_wprojh, b_proj, out, nullptr, CC, CC);
}